// round 11
// baseline (speedup 1.0000x reference)
#include <cuda_runtime.h>
#include <math.h>
#include <stdint.h>

// Problem constants (fixed by the benchmark)
#define BB 64
#define TT 20
#define KK 50
#define EE 100
#define HH 64
#define NROWS (5*BB*KK + 2*BB)    // 16128 gathered rows
#define RROWS 32                  // rows per block in rows role
#define NBLK_ROWS (NROWS/RROWS)   // 504
#define NBLK_BASK (BB*10)         // 640: (b, t-pair), 8 warps

// block-role layout: producers first, then rows/basket INTERLEAVED
#define ROLE_A_BASE    0                   // 64 blocks
#define ROLE_RDA0_BASE (ROLE_A_BASE+BB)    // 64
#define ROLE_P_BASE    (ROLE_RDA0_BASE+BB) // 128
#define ROLE_KES_BASE  (ROLE_P_BASE+BB)    // 192
#define ROLE_MIX_BASE  (ROLE_KES_BASE+BB)  // 256
#define NTOT           (ROLE_MIX_BASE + 2*NBLK_ROWS + (NBLK_BASK-NBLK_ROWS)) // 1400

// ---------------- scratch (no allocations allowed) ----------------
__device__ float g_A[BB*KK*KK];     // A[b,k,j] = alpha_c[k] . rho_c[j]
__device__ float g_rda0[BB*TT*KK];  // rho_c[j] . alpha_item0[t]
__device__ float g_P[BB*TT*KK];     // rho_item0[t] . alpha_c[k]
__device__ float g_ra00[BB*TT];     // rho_item0 . alpha_item0
__device__ float g_kesc[BB*KK];
__device__ float g_kes0[BB*TT];
__device__ float g_part_rows[NBLK_ROWS];
__device__ float g_part_bask[NBLK_BASK];
__device__ unsigned g_ready[BB];    // per-b producer count (4 expected); reset by last block
__device__ unsigned g_count;        // completion ticket; reset by last block

// order-preserving float<->int map (self-inverse)
__device__ __forceinline__ int f_ord(float f) {
    int i = __float_as_int(f);
    return i ^ ((i >> 31) & 0x7FFFFFFF);
}
__device__ __forceinline__ float ord_f(int i) {
    i ^= ((i >> 31) & 0x7FFFFFFF);
    return __int_as_float(i);
}

// ---- basket k-chunk with COMPILE-TIME bounds (unrolled, pipelined) ----
template<int KS, int KE>
__device__ __forceinline__ float basket_chunk(
    const float* __restrict__ sA, unsigned ball0, unsigned ball1, int popA,
    int lane, bool v1, bool mj0, bool mj1,
    float kesc0, float kesc1, float rj0, float rj1,
    float ra00, float kes0v, float px0, float px1)
{
    const unsigned FULL = 0xffffffffu;
    float Cj0 = 0.f, Cj1 = 0.f, acc = 0.f;

    // base: masked prefix over k < KS (cheap, batched LDS)
    #pragma unroll 10
    for (int k = 0; k < KS; k++) {
        float mf = (((k < 32) ? (ball0 >> k) : (ball1 >> (k-32))) & 1u) ? 1.f : 0.f;
        Cj0 = fmaf(mf, sA[k*KK + lane], Cj0);
        if (v1) Cj1 = fmaf(mf, sA[k*KK + 32 + lane], Cj1);
    }
    int cnt;
    if (KS == 0)       cnt = 0;
    else if (KS <= 32) cnt = __popc(ball0 & ((1u << KS) - 1u));
    else               cnt = popA + __popc(ball1 & ((1u << (KS-32)) - 1u));

    // full iterations (fully unrolled; constant designated lanes)
    #pragma unroll
    for (int k = KS; k < KE; k++) {
        bool mk = (((k < 32) ? (ball0 >> k) : (ball1 >> (k-32))) & 1u);
        if (mk) {
            cnt++;
            float ak0 = sA[k*KK + lane];
            float ak1 = v1 ? sA[k*KK + 32 + lane] : 0.f;
            Cj0 += ak0;
            Cj1 += ak1;

            float lenk   = 1.f + (float)cnt;
            float rdenom = __fdividef(1.f, (lenk + 1.f) * (float)EE);

            float c0 = -INFINITY, cc = -INFINITY;
            if (mj0 && lane > k) {
                float bs = rj0 + Cj0;
                c0 = fmaf(bs + rj0, rdenom, kesc0);
                cc = fmaf(bs + ak0, rdenom, kesc0);
            }
            if (mj1 && (lane + 32) > k) {
                float bs = rj1 + Cj1;
                float y0 = fmaf(bs + rj1, rdenom, kesc1);
                float yc = fmaf(bs + ak1, rdenom, kesc1);
                c0 = fmaxf(c0, y0); cc = fmaxf(cc, yc);
            }

            int m0i = __reduce_max_sync(FULL, f_ord(c0));
            int mci = __reduce_max_sync(FULL, f_ord(cc));

            if (lane == (k & 31)) {
                float m0 = ord_f(m0i);
                float mc = ord_f(mci);
                float kescd = (k < 32) ? kesc0 : kesc1;
                float rjd   = (k < 32) ? rj0   : rj1;
                float Cjd   = (k < 32) ? Cj0   : Cj1;
                float Pcd   = (k < 32) ? px0   : px1;
                float inv = __fdividef(1.f, (float)EE * lenk);
                float i0v = (ra00 + Pcd) * inv;
                float icv = (rjd  + Cjd) * inv;
                float Kes0 = kes0v + i0v + fmaxf(0.f, m0);
                float KesC = kescd + icv + fmaxf(0.f, mc);
                float xq = Kes0 - KesC;
                acc += fminf(xq, 0.f) - log1pf(expf(-fabsf(xq)));
            }
        }
    }
    return acc;
}

// =====================================================================
// One fused kernel: producers first; rows & basket interleaved by bid.
// =====================================================================
__global__ void __launch_bounds__(256, 5) fused_kernel(
    const float* __restrict__ alpha, const float* __restrict__ rho,
    const float* __restrict__ lam,   const float* __restrict__ beta,
    const float* __restrict__ mu_tab,const float* __restrict__ theta,
    const float* __restrict__ gamma,
    const float* __restrict__ w1, const float* __restrict__ b1,
    const float* __restrict__ w2, const float* __restrict__ b2,
    const float* __restrict__ sigma, const float* __restrict__ mu,
    const float* __restrict__ prices, const float* __restrict__ price_table,
    const int* __restrict__ item_ids, const int* __restrict__ itemset,
    const int* __restrict__ userid, float* __restrict__ out)
{
    __shared__ __align__(16) char smem_raw[43008];
    __shared__ float ws[8];
    __shared__ double wd[8];
    __shared__ int is_last;
    const unsigned FULL = 0xffffffffu;
    int bx = blockIdx.x, tid = threadIdx.x;

    // role resolution for mixed region
    int rows_idx = -1, bask_idx = -1;
    if (bx >= ROLE_MIX_BASE) {
        int i = bx - ROLE_MIX_BASE;
        if (i < 2*NBLK_ROWS) { if ((i & 1) == 0) rows_idx = i >> 1; else bask_idx = i >> 1; }
        else                 bask_idx = NBLK_ROWS + (i - 2*NBLK_ROWS);
    }

    if (bx < ROLE_RDA0_BASE) {
        // ============ A[b,k,j] Gram, 4x4 tiles ============
        int b = bx - ROLE_A_BASE;
        float* sA = (float*)smem_raw;      // [e][k] pitch 52
        float* sR = sA + EE*52;
        for (int i = tid; i < 2*EE; i += 256) { int e = i >> 1, k = 50 + (i & 1); sA[e*52+k]=0.f; sR[e*52+k]=0.f; }
        for (int i = tid; i < KK*EE; i += 256) {
            int k = i / EE, e = i - k*EE; int row = itemset[b*KK + k];
            sA[e*52 + k] = alpha[(size_t)row*EE + e];
            sR[e*52 + k] = rho  [(size_t)row*EE + e];
        }
        __syncthreads();
        if (tid < 169) {
            int ty = tid / 13, tx = tid - ty*13;
            float acc[4][4] = {};
            for (int e = 0; e < EE; e++) {
                float4 av = *(const float4*)&sA[e*52 + ty*4];
                float4 rv = *(const float4*)&sR[e*52 + tx*4];
                float aa[4] = {av.x, av.y, av.z, av.w};
                float rr[4] = {rv.x, rv.y, rv.z, rv.w};
                #pragma unroll
                for (int i = 0; i < 4; i++)
                    #pragma unroll
                    for (int j = 0; j < 4; j++) acc[i][j] = fmaf(aa[i], rr[j], acc[i][j]);
            }
            #pragma unroll
            for (int i = 0; i < 4; i++) {
                int k = ty*4 + i; if (k >= KK) break;
                #pragma unroll
                for (int j = 0; j < 4; j++) {
                    int jj = tx*4 + j;
                    if (jj < KK) g_A[(b*KK + k)*KK + jj] = acc[i][j];
                }
            }
        }
        __syncthreads();
        if (tid == 0) { __threadfence(); atomicAdd(&g_ready[b], 1u); }

    } else if (bx < ROLE_P_BASE) {
        // ============ rda0[b,t,j] = alpha_item0[t] . rho_c[j] ============
        int b = bx - ROLE_RDA0_BASE;
        float* sR  = (float*)smem_raw;     // [e][j] pitch 52
        float* sA0 = sR + EE*52;           // [e][t] pitch 20
        for (int i = tid; i < 2*EE; i += 256) { int e = i >> 1, k = 50 + (i & 1); sR[e*52+k]=0.f; }
        for (int i = tid; i < KK*EE; i += 256) {
            int k = i / EE, e = i - k*EE; int row = itemset[b*KK + k];
            sR[e*52 + k] = rho[(size_t)row*EE + e];
        }
        for (int i = tid; i < TT*EE; i += 256) {
            int t = i / EE, e = i - t*EE; int row = item_ids[b*TT + t];
            sA0[e*20 + t] = alpha[(size_t)row*EE + e];
        }
        __syncthreads();
        if (tid < 65) {
            int ty = tid / 13, tx = tid - ty*13;
            float acc[4][4] = {};
            for (int e = 0; e < EE; e++) {
                float4 av = *(const float4*)&sA0[e*20 + ty*4];
                float4 rv = *(const float4*)&sR[e*52 + tx*4];
                float aa[4] = {av.x, av.y, av.z, av.w};
                float rr[4] = {rv.x, rv.y, rv.z, rv.w};
                #pragma unroll
                for (int i = 0; i < 4; i++)
                    #pragma unroll
                    for (int j = 0; j < 4; j++) acc[i][j] = fmaf(aa[i], rr[j], acc[i][j]);
            }
            #pragma unroll
            for (int i = 0; i < 4; i++) {
                int t = ty*4 + i;
                #pragma unroll
                for (int j = 0; j < 4; j++) {
                    int jj = tx*4 + j;
                    if (jj < KK) g_rda0[(b*TT + t)*KK + jj] = acc[i][j];
                }
            }
        }
        __syncthreads();
        if (tid == 0) { __threadfence(); atomicAdd(&g_ready[b], 1u); }

    } else if (bx < ROLE_KES_BASE) {
        // ============ P[b,t,k] = rho_item0[t] . alpha_c[k]; ra00 ============
        int b = bx - ROLE_P_BASE;
        float* sAC = (float*)smem_raw;     // [e][k] pitch 52
        float* sR0 = sAC + EE*52;          // [e][t] pitch 20
        float* sA0 = sR0 + EE*20;
        for (int i = tid; i < 2*EE; i += 256) { int e = i >> 1, k = 50 + (i & 1); sAC[e*52+k]=0.f; }
        for (int i = tid; i < KK*EE; i += 256) {
            int k = i / EE, e = i - k*EE; int row = itemset[b*KK + k];
            sAC[e*52 + k] = alpha[(size_t)row*EE + e];
        }
        for (int i = tid; i < TT*EE; i += 256) {
            int t = i / EE, e = i - t*EE; int row = item_ids[b*TT + t];
            sR0[e*20 + t] = rho  [(size_t)row*EE + e];
            sA0[e*20 + t] = alpha[(size_t)row*EE + e];
        }
        __syncthreads();
        if (tid < 65) {
            int ty = tid / 13, tx = tid - ty*13;
            float acc[4][4] = {};
            for (int e = 0; e < EE; e++) {
                float4 rv = *(const float4*)&sR0[e*20 + ty*4];
                float4 av = *(const float4*)&sAC[e*52 + tx*4];
                float rr[4] = {rv.x, rv.y, rv.z, rv.w};
                float aa[4] = {av.x, av.y, av.z, av.w};
                #pragma unroll
                for (int i = 0; i < 4; i++)
                    #pragma unroll
                    for (int j = 0; j < 4; j++) acc[i][j] = fmaf(rr[i], aa[j], acc[i][j]);
            }
            #pragma unroll
            for (int i = 0; i < 4; i++) {
                int t = ty*4 + i;
                #pragma unroll
                for (int j = 0; j < 4; j++) {
                    int kk = tx*4 + j;
                    if (kk < KK) g_P[(b*TT + t)*KK + kk] = acc[i][j];
                }
            }
        }
        if (tid >= 96 && tid < 96 + TT) {
            int t = tid - 96;
            float s = 0.f;
            for (int e = 0; e < EE; e++) s = fmaf(sR0[e*20 + t], sA0[e*20 + t], s);
            g_ra00[b*TT + t] = s;
        }
        __syncthreads();
        if (tid == 0) { __threadfence(); atomicAdd(&g_ready[b], 1u); }

    } else if (bx < ROLE_MIX_BASE) {
        // ============ kes role, one block per b (70 entries, 8 warps) ============
        int b = bx - ROLE_KES_BASE;
        int w = tid >> 5, lane = tid & 31;
        int u = userid[b];
        const float* th = theta + (size_t)u*EE;
        const float* ga = gamma + (size_t)u*EE;
        float th0 = th[lane], th1 = th[32+lane], th2 = th[64+lane];
        float ga0 = ga[lane], ga1 = ga[32+lane], ga2 = ga[64+lane];
        float th3 = (lane < 4) ? th[96+lane] : 0.f;
        float ga3 = (lane < 4) ? ga[96+lane] : 0.f;

        for (int e = w; e < KK + TT; e += 8) {
            int idx; float price; bool is_c = (e < KK);
            if (is_c) { idx = itemset[b*KK + e]; price = price_table[idx]; }
            else      { int t = e - KK; idx = item_ids[b*TT + t]; price = prices[b*TT + t]; }
            const float* a  = alpha + (size_t)idx*EE;
            const float* l  = lam   + (size_t)idx*EE;
            const float* be = beta  + (size_t)idx*EE;
            float a0 = a[lane], a1 = a[32+lane], a2 = a[64+lane];
            float l0 = l[lane], l1 = l[32+lane], l2 = l[64+lane];
            float be0 = be[lane], be1 = be[32+lane], be2 = be[64+lane];
            float a3 = 0.f, l3 = 0.f, be3 = 0.f;
            if (lane < 4) { a3 = a[96+lane]; l3 = l[96+lane]; be3 = be[96+lane]; }

            float s1 = l0 + l1 + l2 + l3;
            float s2 = fmaf(th0,a0, fmaf(th1,a1, fmaf(th2,a2, th3*a3)));
            float s3 = fmaf(ga0,be0, fmaf(ga1,be1, fmaf(ga2,be2, ga3*be3)));
            #pragma unroll
            for (int o = 16; o; o >>= 1) {
                s1 += __shfl_xor_sync(FULL, s1, o);
                s2 += __shfl_xor_sync(FULL, s2, o);
                s3 += __shfl_xor_sync(FULL, s3, o);
            }
            if (lane == 0) {
                float val = (s1 + s2) * (1.f/EE) - (s3 * (1.f/EE)) * logf(price);
                if (is_c) g_kesc[b*KK + e] = val; else g_kes0[b*TT + (e - KK)] = val;
            }
        }
        __syncthreads();
        if (tid == 0) { __threadfence(); atomicAdd(&g_ready[b], 1u); }

    } else if (rows_idx >= 0) {
        // ============ rows role: Qf + prior over 32 gathered rows ============
        float* w1t   = (float*)smem_raw;        // [e][h] pitch 68 (6800)
        float* v_rm  = w1t + EE*68;             // [e][row] pitch 34 (3400)
        float* ssrow = v_rm + EE*34;            // 32
        float* w2s   = ssrow + RROWS;           // 64
        float* b1s   = w2s + HH;                // 64
        float* bsum  = b1s + HH;                // 1

        int base = rows_idx * RROWS;
        int g; const float* tab; int uoff = 0;
        if (base < 5*BB*KK) {
            g = base / (BB*KK);
            tab = (g==0)?alpha : (g==1)?rho : (g==2)?lam : (g==3)?beta : mu_tab;
        } else if (base < 5*BB*KK + BB) { g = 5; tab = theta; uoff = base - 5*BB*KK; }
        else                            { g = 6; tab = gamma; uoff = base - 5*BB*KK - BB; }
        float sg = sigma[g], muv = mu[g];
        float b2v = b2[0];

        for (int i = tid; i < HH*EE; i += 256) {
            int h = i / EE, e = i - h*EE;
            w1t[e*68 + h] = w1[i];
        }
        if (tid < HH) { w2s[tid] = w2[tid]; b1s[tid] = b1[tid]; }
        if (tid == 0) *bsum = 0.f;

        for (int i = tid; i < RROWS*EE; i += 256) {
            int rl = i / EE, e = i - rl*EE;
            int idx;
            if (g < 5) idx = itemset[base - g*(BB*KK) + rl];
            else       idx = userid[uoff + rl];
            v_rm[e*34 + rl] = tab[(size_t)idx*EE + e];   // transposed store
        }
        __syncthreads();

        if (tid < RROWS) {
            float ss = 0.f;
            for (int e = 0; e < EE; e++) { float x = v_rm[e*34 + tid] - muv; ss = fmaf(x, x, ss); }
            ssrow[tid] = ss;
        }

        int ty = tid >> 4, tx = tid & 15;   // rows 2ty,2ty+1; hidden tx*4..+3
        float acc[2][4];
        #pragma unroll
        for (int i = 0; i < 2; i++)
            #pragma unroll
            for (int j = 0; j < 4; j++) acc[i][j] = b1s[tx*4 + j];

        #pragma unroll 2
        for (int e = 0; e < EE; e++) {
            float4 wv = *(const float4*)&w1t[e*68 + tx*4];
            float2 vv = *(const float2*)&v_rm[e*34 + 2*ty];
            acc[0][0] = fmaf(vv.x, wv.x, acc[0][0]);
            acc[0][1] = fmaf(vv.x, wv.y, acc[0][1]);
            acc[0][2] = fmaf(vv.x, wv.z, acc[0][2]);
            acc[0][3] = fmaf(vv.x, wv.w, acc[0][3]);
            acc[1][0] = fmaf(vv.y, wv.x, acc[1][0]);
            acc[1][1] = fmaf(vv.y, wv.y, acc[1][1]);
            acc[1][2] = fmaf(vv.y, wv.z, acc[1][2]);
            acc[1][3] = fmaf(vv.y, wv.w, acc[1][3]);
        }

        float z[2];
        #pragma unroll
        for (int i = 0; i < 2; i++) {
            float s = 0.f;
            #pragma unroll
            for (int j = 0; j < 4; j++) s = fmaf(fmaxf(acc[i][j], 0.f), w2s[tx*4 + j], s);
            z[i] = s;
        }
        #pragma unroll
        for (int o = 8; o; o >>= 1) {
            z[0] += __shfl_xor_sync(FULL, z[0], o);
            z[1] += __shfl_xor_sync(FULL, z[1], o);
        }
        __syncthreads();
        if (tx == 0) {
            float local = 0.f;
            #pragma unroll
            for (int i = 0; i < 2; i++) {
                float q = 1.f / (1.f + expf(-(z[i] + b2v)));
                local += (-0.5f/sg)*ssrow[2*ty + i] - q;
            }
            atomicAdd(bsum, local);
        }
        __syncthreads();
        if (tid == 0) g_part_rows[rows_idx] = *bsum;

    } else {
        // ============ basket role: 2 t's x 4 k-chunks per block ============
        int bx2 = bask_idx;                 // 0..639
        int b = bx2 / 10, pair = bx2 % 10;
        int w = tid >> 5, lane = tid & 31;
        int sub = w >> 2, chunk = w & 3;
        int t = pair*2 + sub;
        int bt = b*TT + t;
        int base = b*KK;

        int item0 = item_ids[bt];
        bool v1 = (lane < KK - 32);
        int c0i = itemset[base + lane];
        int c1i = v1 ? itemset[base + 32 + lane] : 0;
        bool mj0 = (c0i != item0);
        bool mj1 = v1 && (c1i != item0);
        unsigned ball0 = __ballot_sync(FULL, mj0);
        unsigned ball1 = __ballot_sync(FULL, mj1);
        int popA = __popc(ball0);

        // wait for this b's producers (A, rda0, P, kes)
        if (tid == 0) {
            volatile unsigned* f = &g_ready[b];
            while (*f < 4u) __nanosleep(64);
        }
        __syncthreads();
        __threadfence();

        float* sA = (float*)smem_raw;       // A[b] [k][j], 10KB
        for (int i = tid; i < KK*KK; i += 256) sA[i] = g_A[base*KK + i];

        float kesc0 = g_kesc[base + lane];
        float kesc1 = v1 ? g_kesc[base + 32 + lane] : 0.f;
        float rj0 = g_rda0[bt*KK + lane];
        float rj1 = v1 ? g_rda0[bt*KK + 32 + lane] : 0.f;
        float ra00  = g_ra00[bt];
        float kes0v = g_kes0[bt];

        // one-time masked inclusive prefix scan of P over k (two 32-halves)
        float px0 = mj0 ? g_P[bt*KK + lane] : 0.f;
        float px1 = mj1 ? g_P[bt*KK + 32 + lane] : 0.f;
        #pragma unroll
        for (int d = 1; d < 32; d <<= 1) {
            float v = __shfl_up_sync(FULL, px0, d);
            if (lane >= d) px0 += v;
        }
        float tot0 = __shfl_sync(FULL, px0, 31);
        #pragma unroll
        for (int d = 1; d < 32; d <<= 1) {
            float v = __shfl_up_sync(FULL, px1, d);
            if (lane >= d) px1 += v;
        }
        px1 += tot0;

        __syncthreads();   // sA ready

        // balanced chunk bounds by cost KS + 3*(KE-KS): {0,21,35,44,50}
        float acc;
        switch (chunk) {
            case 0:  acc = basket_chunk< 0,21>(sA, ball0, ball1, popA, lane, v1, mj0, mj1,
                                               kesc0, kesc1, rj0, rj1, ra00, kes0v, px0, px1); break;
            case 1:  acc = basket_chunk<21,35>(sA, ball0, ball1, popA, lane, v1, mj0, mj1,
                                               kesc0, kesc1, rj0, rj1, ra00, kes0v, px0, px1); break;
            case 2:  acc = basket_chunk<35,44>(sA, ball0, ball1, popA, lane, v1, mj0, mj1,
                                               kesc0, kesc1, rj0, rj1, ra00, kes0v, px0, px1); break;
            default: acc = basket_chunk<44,50>(sA, ball0, ball1, popA, lane, v1, mj0, mj1,
                                               kesc0, kesc1, rj0, rj1, ra00, kes0v, px0, px1); break;
        }

        #pragma unroll
        for (int o = 16; o; o >>= 1) acc += __shfl_xor_sync(FULL, acc, o);
        if (lane == 0) ws[w] = acc;
        __syncthreads();
        if (tid == 0) {
            float s = 0.f;
            #pragma unroll
            for (int i = 0; i < 8; i++) s += ws[i];
            g_part_bask[bx2] = s;
        }
    }

    // ================= common epilogue: completion ticket =================
    __syncthreads();
    if (tid == 0) {
        __threadfence();
        unsigned tk = atomicAdd(&g_count, 1u);
        is_last = (tk == NTOT - 1) ? 1 : 0;
    }
    __syncthreads();

    if (is_last) {
        __threadfence();  // see all blocks' partial stores
        double s = 0.0;
        for (int i = tid; i < NBLK_ROWS; i += 256) s += (double)g_part_rows[i];
        for (int i = tid; i < NBLK_BASK; i += 256) s += (double)g_part_bask[i];
        #pragma unroll
        for (int o = 16; o; o >>= 1) s += __shfl_xor_sync(FULL, s, o);
        if ((tid & 31) == 0) wd[tid >> 5] = s;
        __syncthreads();
        if (tid == 0) {
            double tt = 0.0;
            #pragma unroll
            for (int i = 0; i < 8; i++) tt += wd[i];
            out[0] = (float)tt;
            g_count = 0u;                       // reset for next replay
        }
        if (tid < BB) g_ready[tid] = 0u;        // reset flags for next replay
    }
}

// ================= launch: ONE node, no driver objects ================
extern "C" void kernel_launch(void* const* d_in, const int* in_sizes, int n_in,
                              void* d_out, int out_size)
{
    const float* alpha       = (const float*)d_in[0];
    const float* rho         = (const float*)d_in[1];
    const float* lam         = (const float*)d_in[2];
    const float* beta        = (const float*)d_in[3];
    const float* mu_tab      = (const float*)d_in[4];
    const float* theta       = (const float*)d_in[5];
    const float* gamma       = (const float*)d_in[6];
    const float* w1          = (const float*)d_in[7];
    const float* b1          = (const float*)d_in[8];
    const float* w2          = (const float*)d_in[9];
    const float* b2          = (const float*)d_in[10];
    const float* sigma_list  = (const float*)d_in[11];
    const float* mu_list     = (const float*)d_in[12];
    const float* prices      = (const float*)d_in[13];
    const float* price_table = (const float*)d_in[14];
    const int*   item_ids    = (const int*)d_in[15];
    const int*   itemset     = (const int*)d_in[16];
    const int*   userid      = (const int*)d_in[17];

    fused_kernel<<<NTOT, 256>>>(alpha, rho, lam, beta, mu_tab, theta, gamma,
                                w1, b1, w2, b2, sigma_list, mu_list,
                                prices, price_table, item_ids, itemset, userid,
                                (float*)d_out);
}

// round 12
// speedup vs baseline: 1.2140x; 1.2140x over previous
#include <cuda_runtime.h>
#include <math.h>
#include <stdint.h>

// Problem constants (fixed by the benchmark)
#define BB 64
#define TT 20
#define KK 50
#define EE 100
#define HH 64
#define NROWS (5*BB*KK + 2*BB)    // 16128 gathered rows
#define RROWS 32                  // rows per block in rows role
#define NBLK_ROWS (NROWS/RROWS)   // 504
#define NBLK_BASK (BB*10)         // 640: (b, t-pair), 8 warps

// block-role layout: producers first, then rows/basket strictly alternating
#define ROLE_A_BASE    0                   // 64 blocks
#define ROLE_RDA0_BASE (ROLE_A_BASE+BB)    // 64
#define ROLE_P_BASE    (ROLE_RDA0_BASE+BB) // 128
#define ROLE_KES_BASE  (ROLE_P_BASE+BB)    // 192
#define ROLE_MIX_BASE  (ROLE_KES_BASE+BB)  // 256
#define NTOT           (ROLE_MIX_BASE + NBLK_ROWS + NBLK_BASK) // 1400

// ---------------- scratch (no allocations allowed) ----------------
__device__ float g_A[BB*KK*KK];     // A[b,k,j] = alpha_c[k] . rho_c[j]
__device__ float g_rda0[BB*TT*KK];  // rho_c[j] . alpha_item0[t]
__device__ float g_P[BB*TT*KK];     // rho_item0[t] . alpha_c[k]
__device__ float g_ra00[BB*TT];     // rho_item0 . alpha_item0
__device__ float g_kesc[BB*KK];
__device__ float g_kes0[BB*TT];
__device__ float g_part_rows[NBLK_ROWS];
__device__ float g_part_bask[NBLK_BASK];
__device__ unsigned g_ready[BB];    // per-b producer count (4 expected); reset by last block
__device__ unsigned g_count;        // completion ticket; reset by last block

// order-preserving float<->int map (self-inverse)
__device__ __forceinline__ int f_ord(float f) {
    int i = __float_as_int(f);
    return i ^ ((i >> 31) & 0x7FFFFFFF);
}
__device__ __forceinline__ float ord_f(int i) {
    i ^= ((i >> 31) & 0x7FFFFFFF);
    return __int_as_float(i);
}

// =====================================================================
// One fused kernel: producers first; rows & basket interleaved by bid;
// role bodies identical to the validated 45.1us kernel (compact code).
// =====================================================================
__global__ void __launch_bounds__(256, 5) fused_kernel(
    const float* __restrict__ alpha, const float* __restrict__ rho,
    const float* __restrict__ lam,   const float* __restrict__ beta,
    const float* __restrict__ mu_tab,const float* __restrict__ theta,
    const float* __restrict__ gamma,
    const float* __restrict__ w1, const float* __restrict__ b1,
    const float* __restrict__ w2, const float* __restrict__ b2,
    const float* __restrict__ sigma, const float* __restrict__ mu,
    const float* __restrict__ prices, const float* __restrict__ price_table,
    const int* __restrict__ item_ids, const int* __restrict__ itemset,
    const int* __restrict__ userid, float* __restrict__ out)
{
    __shared__ __align__(16) char smem_raw[43008];
    __shared__ float ws[8];
    __shared__ double wd[8];
    __shared__ int is_last;
    const unsigned FULL = 0xffffffffu;
    int bx = blockIdx.x, tid = threadIdx.x;

    // role resolution for mixed region (strict alternation, then basket tail)
    int rows_idx = -1, bask_idx = -1;
    if (bx >= ROLE_MIX_BASE) {
        int i = bx - ROLE_MIX_BASE;
        if (i < 2*NBLK_ROWS) { if ((i & 1) == 0) rows_idx = i >> 1; else bask_idx = i >> 1; }
        else                 bask_idx = NBLK_ROWS + (i - 2*NBLK_ROWS);
    }

    if (bx < ROLE_RDA0_BASE) {
        // ============ A[b,k,j] Gram, 4x4 tiles ============
        int b = bx - ROLE_A_BASE;
        float* sA = (float*)smem_raw;      // [e][k] pitch 52
        float* sR = sA + EE*52;
        for (int i = tid; i < 2*EE; i += 256) { int e = i >> 1, k = 50 + (i & 1); sA[e*52+k]=0.f; sR[e*52+k]=0.f; }
        for (int i = tid; i < KK*EE; i += 256) {
            int k = i / EE, e = i - k*EE; int row = itemset[b*KK + k];
            sA[e*52 + k] = alpha[(size_t)row*EE + e];
            sR[e*52 + k] = rho  [(size_t)row*EE + e];
        }
        __syncthreads();
        if (tid < 169) {
            int ty = tid / 13, tx = tid - ty*13;
            float acc[4][4] = {};
            for (int e = 0; e < EE; e++) {
                float4 av = *(const float4*)&sA[e*52 + ty*4];
                float4 rv = *(const float4*)&sR[e*52 + tx*4];
                float aa[4] = {av.x, av.y, av.z, av.w};
                float rr[4] = {rv.x, rv.y, rv.z, rv.w};
                #pragma unroll
                for (int i = 0; i < 4; i++)
                    #pragma unroll
                    for (int j = 0; j < 4; j++) acc[i][j] = fmaf(aa[i], rr[j], acc[i][j]);
            }
            #pragma unroll
            for (int i = 0; i < 4; i++) {
                int k = ty*4 + i; if (k >= KK) break;
                #pragma unroll
                for (int j = 0; j < 4; j++) {
                    int jj = tx*4 + j;
                    if (jj < KK) g_A[(b*KK + k)*KK + jj] = acc[i][j];
                }
            }
        }
        __syncthreads();
        if (tid == 0) { __threadfence(); atomicAdd(&g_ready[b], 1u); }

    } else if (bx < ROLE_P_BASE) {
        // ============ rda0[b,t,j] = alpha_item0[t] . rho_c[j] ============
        int b = bx - ROLE_RDA0_BASE;
        float* sR  = (float*)smem_raw;     // [e][j] pitch 52
        float* sA0 = sR + EE*52;           // [e][t] pitch 20
        for (int i = tid; i < 2*EE; i += 256) { int e = i >> 1, k = 50 + (i & 1); sR[e*52+k]=0.f; }
        for (int i = tid; i < KK*EE; i += 256) {
            int k = i / EE, e = i - k*EE; int row = itemset[b*KK + k];
            sR[e*52 + k] = rho[(size_t)row*EE + e];
        }
        for (int i = tid; i < TT*EE; i += 256) {
            int t = i / EE, e = i - t*EE; int row = item_ids[b*TT + t];
            sA0[e*20 + t] = alpha[(size_t)row*EE + e];
        }
        __syncthreads();
        if (tid < 65) {
            int ty = tid / 13, tx = tid - ty*13;
            float acc[4][4] = {};
            for (int e = 0; e < EE; e++) {
                float4 av = *(const float4*)&sA0[e*20 + ty*4];
                float4 rv = *(const float4*)&sR[e*52 + tx*4];
                float aa[4] = {av.x, av.y, av.z, av.w};
                float rr[4] = {rv.x, rv.y, rv.z, rv.w};
                #pragma unroll
                for (int i = 0; i < 4; i++)
                    #pragma unroll
                    for (int j = 0; j < 4; j++) acc[i][j] = fmaf(aa[i], rr[j], acc[i][j]);
            }
            #pragma unroll
            for (int i = 0; i < 4; i++) {
                int t = ty*4 + i;
                #pragma unroll
                for (int j = 0; j < 4; j++) {
                    int jj = tx*4 + j;
                    if (jj < KK) g_rda0[(b*TT + t)*KK + jj] = acc[i][j];
                }
            }
        }
        __syncthreads();
        if (tid == 0) { __threadfence(); atomicAdd(&g_ready[b], 1u); }

    } else if (bx < ROLE_KES_BASE) {
        // ============ P[b,t,k] = rho_item0[t] . alpha_c[k]; ra00 ============
        int b = bx - ROLE_P_BASE;
        float* sAC = (float*)smem_raw;     // [e][k] pitch 52
        float* sR0 = sAC + EE*52;          // [e][t] pitch 20
        float* sA0 = sR0 + EE*20;
        for (int i = tid; i < 2*EE; i += 256) { int e = i >> 1, k = 50 + (i & 1); sAC[e*52+k]=0.f; }
        for (int i = tid; i < KK*EE; i += 256) {
            int k = i / EE, e = i - k*EE; int row = itemset[b*KK + k];
            sAC[e*52 + k] = alpha[(size_t)row*EE + e];
        }
        for (int i = tid; i < TT*EE; i += 256) {
            int t = i / EE, e = i - t*EE; int row = item_ids[b*TT + t];
            sR0[e*20 + t] = rho  [(size_t)row*EE + e];
            sA0[e*20 + t] = alpha[(size_t)row*EE + e];
        }
        __syncthreads();
        if (tid < 65) {
            int ty = tid / 13, tx = tid - ty*13;
            float acc[4][4] = {};
            for (int e = 0; e < EE; e++) {
                float4 rv = *(const float4*)&sR0[e*20 + ty*4];
                float4 av = *(const float4*)&sAC[e*52 + tx*4];
                float rr[4] = {rv.x, rv.y, rv.z, rv.w};
                float aa[4] = {av.x, av.y, av.z, av.w};
                #pragma unroll
                for (int i = 0; i < 4; i++)
                    #pragma unroll
                    for (int j = 0; j < 4; j++) acc[i][j] = fmaf(rr[i], aa[j], acc[i][j]);
            }
            #pragma unroll
            for (int i = 0; i < 4; i++) {
                int t = ty*4 + i;
                #pragma unroll
                for (int j = 0; j < 4; j++) {
                    int kk = tx*4 + j;
                    if (kk < KK) g_P[(b*TT + t)*KK + kk] = acc[i][j];
                }
            }
        }
        if (tid >= 96 && tid < 96 + TT) {
            int t = tid - 96;
            float s = 0.f;
            for (int e = 0; e < EE; e++) s = fmaf(sR0[e*20 + t], sA0[e*20 + t], s);
            g_ra00[b*TT + t] = s;
        }
        __syncthreads();
        if (tid == 0) { __threadfence(); atomicAdd(&g_ready[b], 1u); }

    } else if (bx < ROLE_MIX_BASE) {
        // ============ kes role, one block per b (70 entries, 8 warps) ============
        int b = bx - ROLE_KES_BASE;
        int w = tid >> 5, lane = tid & 31;
        int u = userid[b];
        const float* th = theta + (size_t)u*EE;
        const float* ga = gamma + (size_t)u*EE;
        float th0 = th[lane], th1 = th[32+lane], th2 = th[64+lane];
        float ga0 = ga[lane], ga1 = ga[32+lane], ga2 = ga[64+lane];
        float th3 = (lane < 4) ? th[96+lane] : 0.f;
        float ga3 = (lane < 4) ? ga[96+lane] : 0.f;

        for (int e = w; e < KK + TT; e += 8) {
            int idx; float price; bool is_c = (e < KK);
            if (is_c) { idx = itemset[b*KK + e]; price = price_table[idx]; }
            else      { int t = e - KK; idx = item_ids[b*TT + t]; price = prices[b*TT + t]; }
            const float* a  = alpha + (size_t)idx*EE;
            const float* l  = lam   + (size_t)idx*EE;
            const float* be = beta  + (size_t)idx*EE;
            float a0 = a[lane], a1 = a[32+lane], a2 = a[64+lane];
            float l0 = l[lane], l1 = l[32+lane], l2 = l[64+lane];
            float be0 = be[lane], be1 = be[32+lane], be2 = be[64+lane];
            float a3 = 0.f, l3 = 0.f, be3 = 0.f;
            if (lane < 4) { a3 = a[96+lane]; l3 = l[96+lane]; be3 = be[96+lane]; }

            float s1 = l0 + l1 + l2 + l3;
            float s2 = fmaf(th0,a0, fmaf(th1,a1, fmaf(th2,a2, th3*a3)));
            float s3 = fmaf(ga0,be0, fmaf(ga1,be1, fmaf(ga2,be2, ga3*be3)));
            #pragma unroll
            for (int o = 16; o; o >>= 1) {
                s1 += __shfl_xor_sync(FULL, s1, o);
                s2 += __shfl_xor_sync(FULL, s2, o);
                s3 += __shfl_xor_sync(FULL, s3, o);
            }
            if (lane == 0) {
                float val = (s1 + s2) * (1.f/EE) - (s3 * (1.f/EE)) * logf(price);
                if (is_c) g_kesc[b*KK + e] = val; else g_kes0[b*TT + (e - KK)] = val;
            }
        }
        __syncthreads();
        if (tid == 0) { __threadfence(); atomicAdd(&g_ready[b], 1u); }

    } else if (rows_idx >= 0) {
        // ============ rows role: Qf + prior over 32 gathered rows ============
        float* w1t   = (float*)smem_raw;        // [e][h] pitch 68
        float* v_rm  = w1t + EE*68;             // [row][e]
        float* ssrow = v_rm + RROWS*EE;
        float* w2s   = ssrow + RROWS;
        float* b1s   = w2s + HH;
        float* bsum  = b1s + HH;

        int base = rows_idx * RROWS;
        int g; const float* tab; int uoff = 0;
        if (base < 5*BB*KK) {
            g = base / (BB*KK);
            tab = (g==0)?alpha : (g==1)?rho : (g==2)?lam : (g==3)?beta : mu_tab;
        } else if (base < 5*BB*KK + BB) { g = 5; tab = theta; uoff = base - 5*BB*KK; }
        else                            { g = 6; tab = gamma; uoff = base - 5*BB*KK - BB; }
        float sg = sigma[g], muv = mu[g];
        float b2v = b2[0];

        for (int i = tid; i < HH*EE; i += 256) {
            int h = i / EE, e = i - h*EE;
            w1t[e*68 + h] = w1[i];
        }
        if (tid < HH) { w2s[tid] = w2[tid]; b1s[tid] = b1[tid]; }
        if (tid == 0) *bsum = 0.f;

        for (int i = tid; i < RROWS*EE; i += 256) {
            int rl = i / EE, e = i - rl*EE;
            int idx;
            if (g < 5) idx = itemset[base - g*(BB*KK) + rl];
            else       idx = userid[uoff + rl];
            v_rm[rl*EE + e] = tab[(size_t)idx*EE + e];
        }
        __syncthreads();

        if (tid < RROWS) {
            float ss = 0.f;
            for (int e = 0; e < EE; e++) { float x = v_rm[tid*EE + e] - muv; ss = fmaf(x, x, ss); }
            ssrow[tid] = ss;
        }

        int ty = tid >> 4, tx = tid & 15;
        float acc[2][4];
        #pragma unroll
        for (int i = 0; i < 2; i++)
            #pragma unroll
            for (int j = 0; j < 4; j++) acc[i][j] = b1s[tx*4 + j];

        for (int e = 0; e < EE; e++) {
            float4 wv = *(const float4*)&w1t[e*68 + tx*4];
            float vv0 = v_rm[(2*ty + 0)*EE + e];
            float vv1 = v_rm[(2*ty + 1)*EE + e];
            acc[0][0] = fmaf(vv0, wv.x, acc[0][0]);
            acc[0][1] = fmaf(vv0, wv.y, acc[0][1]);
            acc[0][2] = fmaf(vv0, wv.z, acc[0][2]);
            acc[0][3] = fmaf(vv0, wv.w, acc[0][3]);
            acc[1][0] = fmaf(vv1, wv.x, acc[1][0]);
            acc[1][1] = fmaf(vv1, wv.y, acc[1][1]);
            acc[1][2] = fmaf(vv1, wv.z, acc[1][2]);
            acc[1][3] = fmaf(vv1, wv.w, acc[1][3]);
        }

        float z[2];
        #pragma unroll
        for (int i = 0; i < 2; i++) {
            float s = 0.f;
            #pragma unroll
            for (int j = 0; j < 4; j++) s = fmaf(fmaxf(acc[i][j], 0.f), w2s[tx*4 + j], s);
            z[i] = s;
        }
        #pragma unroll
        for (int o = 8; o; o >>= 1) {
            z[0] += __shfl_xor_sync(FULL, z[0], o);
            z[1] += __shfl_xor_sync(FULL, z[1], o);
        }
        __syncthreads();
        if (tx == 0) {
            float local = 0.f;
            #pragma unroll
            for (int i = 0; i < 2; i++) {
                float q = 1.f / (1.f + expf(-(z[i] + b2v)));
                local += (-0.5f/sg)*ssrow[2*ty + i] - q;
            }
            atomicAdd(bsum, local);
        }
        __syncthreads();
        if (tid == 0) g_part_rows[rows_idx] = *bsum;

    } else {
        // ============ basket role: 2 t's x 4 k-chunks per block ============
        int bx2 = bask_idx;                 // 0..639
        int b = bx2 / 10, pair = bx2 % 10;
        int w = tid >> 5, lane = tid & 31;
        int sub = w >> 2, chunk = w & 3;
        int t = pair*2 + sub;
        int bt = b*TT + t;
        int base = b*KK;
        // balanced chunk bounds by cost KS + 3*(KE-KS): {0,21,35,44,50}
        int kstart = (chunk==0) ? 0  : (chunk==1) ? 21 : (chunk==2) ? 35 : 44;
        int kend   = (chunk==0) ? 21 : (chunk==1) ? 35 : (chunk==2) ? 44 : 50;

        // inputs not produced in-kernel can be read pre-wait
        int item0 = item_ids[bt];
        bool v1 = (lane < KK - 32);
        int c0i = itemset[base + lane];
        int c1i = v1 ? itemset[base + 32 + lane] : 0;
        bool mj0 = (c0i != item0);
        bool mj1 = v1 && (c1i != item0);
        unsigned ball0 = __ballot_sync(FULL, mj0);
        unsigned ball1 = __ballot_sync(FULL, mj1);
        int popA = __popc(ball0);

        // wait for this b's producers (A, rda0, P, kes)
        if (tid == 0) {
            volatile unsigned* f = &g_ready[b];
            while (*f < 4u) __nanosleep(64);
        }
        __syncthreads();
        __threadfence();

        float* sA = (float*)smem_raw;       // A[b] [k][j], 10KB
        for (int i = tid; i < KK*KK; i += 256) sA[i] = g_A[base*KK + i];

        float kesc0 = g_kesc[base + lane];
        float kesc1 = v1 ? g_kesc[base + 32 + lane] : 0.f;
        float rj0 = g_rda0[bt*KK + lane];
        float rj1 = v1 ? g_rda0[bt*KK + 32 + lane] : 0.f;
        float ra00  = g_ra00[bt];
        float kes0v = g_kes0[bt];

        // one-time masked inclusive prefix scan of P over k (two 32-halves)
        float px0 = mj0 ? g_P[bt*KK + lane] : 0.f;
        float px1 = mj1 ? g_P[bt*KK + 32 + lane] : 0.f;
        #pragma unroll
        for (int d = 1; d < 32; d <<= 1) {
            float v = __shfl_up_sync(FULL, px0, d);
            if (lane >= d) px0 += v;
        }
        float tot0 = __shfl_sync(FULL, px0, 31);
        #pragma unroll
        for (int d = 1; d < 32; d <<= 1) {
            float v = __shfl_up_sync(FULL, px1, d);
            if (lane >= d) px1 += v;
        }
        px1 += tot0;

        __syncthreads();   // sA ready

        // chunk base: Cj up to kstart (cheap pipelined masked FMAs)
        float Cj0 = 0.f, Cj1 = 0.f, acc = 0.f;
        for (int k = 0; k < kstart; k++) {
            float mf = ((k < 32 ? (ball0 >> k) : (ball1 >> (k-32))) & 1u) ? 1.f : 0.f;
            Cj0 = fmaf(mf, sA[k*KK + lane], Cj0);
            if (v1) Cj1 = fmaf(mf, sA[k*KK + 32 + lane], Cj1);
        }
        // running count of set bits strictly below kstart
        int cnt;
        if (kstart == 0)        cnt = 0;
        else if (kstart <= 32)  cnt = __popc(ball0 & ((1u << kstart) - 1u));
        else                    cnt = popA + __popc(ball1 & ((1u << (kstart-32)) - 1u));

        for (int k = kstart; k < kend; k++) {
            bool mk = ((k < 32 ? (ball0 >> k) : (ball1 >> (k-32))) & 1u);
            if (mk) {   // uniform branch; when item0 == c_k the step is a no-op
                cnt++;
                float ak0 = sA[k*KK + lane];
                float ak1 = v1 ? sA[k*KK + 32 + lane] : 0.f;
                Cj0 += ak0;
                Cj1 += ak1;

                float lenk   = 1.f + (float)cnt;
                float rdenom = __fdividef(1.f, (lenk + 1.f) * (float)EE);

                float c0 = -INFINITY, cc = -INFINITY;
                if (mj0 && lane > k) {
                    float bs = rj0 + Cj0;
                    c0 = fmaf(bs + rj0, rdenom, kesc0);
                    cc = fmaf(bs + ak0, rdenom, kesc0);
                }
                if (mj1 && (lane + 32) > k) {
                    float bs = rj1 + Cj1;
                    float y0 = fmaf(bs + rj1, rdenom, kesc1);
                    float yc = fmaf(bs + ak1, rdenom, kesc1);
                    c0 = fmaxf(c0, y0); cc = fmaxf(cc, yc);
                }

                int m0i = __reduce_max_sync(FULL, f_ord(c0));
                int mci = __reduce_max_sync(FULL, f_ord(cc));

                if (lane == (k & 31)) {     // designated j==k; mjd == mk == true here
                    float m0 = ord_f(m0i);
                    float mc = ord_f(mci);
                    float kescd = (k < 32) ? kesc0 : kesc1;
                    float rjd   = (k < 32) ? rj0   : rj1;
                    float Cjd   = (k < 32) ? Cj0   : Cj1;
                    float Pcd   = (k < 32) ? px0   : px1;
                    float inv = __fdividef(1.f, (float)EE * lenk);
                    float i0v = (ra00 + Pcd) * inv;
                    float icv = (rjd  + Cjd) * inv;
                    float Kes0 = kes0v + i0v + fmaxf(0.f, m0);
                    float KesC = kescd + icv + fmaxf(0.f, mc);
                    float xq = Kes0 - KesC;
                    acc += fminf(xq, 0.f) - log1pf(expf(-fabsf(xq)));
                }
            }
        }

        #pragma unroll
        for (int o = 16; o; o >>= 1) acc += __shfl_xor_sync(FULL, acc, o);
        if (lane == 0) ws[w] = acc;
        __syncthreads();
        if (tid == 0) {
            float s = 0.f;
            #pragma unroll
            for (int i = 0; i < 8; i++) s += ws[i];
            g_part_bask[bx2] = s;
        }
    }

    // ================= common epilogue: completion ticket =================
    __syncthreads();
    if (tid == 0) {
        __threadfence();
        unsigned tk = atomicAdd(&g_count, 1u);
        is_last = (tk == NTOT - 1) ? 1 : 0;
    }
    __syncthreads();

    if (is_last) {
        __threadfence();  // see all blocks' partial stores
        double s = 0.0;
        for (int i = tid; i < NBLK_ROWS; i += 256) s += (double)g_part_rows[i];
        for (int i = tid; i < NBLK_BASK; i += 256) s += (double)g_part_bask[i];
        #pragma unroll
        for (int o = 16; o; o >>= 1) s += __shfl_xor_sync(FULL, s, o);
        if ((tid & 31) == 0) wd[tid >> 5] = s;
        __syncthreads();
        if (tid == 0) {
            double tt = 0.0;
            #pragma unroll
            for (int i = 0; i < 8; i++) tt += wd[i];
            out[0] = (float)tt;
            g_count = 0u;                       // reset for next replay
        }
        if (tid < BB) g_ready[tid] = 0u;        // reset flags for next replay
    }
}

// ================= launch: ONE node, no driver objects ================
extern "C" void kernel_launch(void* const* d_in, const int* in_sizes, int n_in,
                              void* d_out, int out_size)
{
    const float* alpha       = (const float*)d_in[0];
    const float* rho         = (const float*)d_in[1];
    const float* lam         = (const float*)d_in[2];
    const float* beta        = (const float*)d_in[3];
    const float* mu_tab      = (const float*)d_in[4];
    const float* theta       = (const float*)d_in[5];
    const float* gamma       = (const float*)d_in[6];
    const float* w1          = (const float*)d_in[7];
    const float* b1          = (const float*)d_in[8];
    const float* w2          = (const float*)d_in[9];
    const float* b2          = (const float*)d_in[10];
    const float* sigma_list  = (const float*)d_in[11];
    const float* mu_list     = (const float*)d_in[12];
    const float* prices      = (const float*)d_in[13];
    const float* price_table = (const float*)d_in[14];
    const int*   item_ids    = (const int*)d_in[15];
    const int*   itemset     = (const int*)d_in[16];
    const int*   userid      = (const int*)d_in[17];

    fused_kernel<<<NTOT, 256>>>(alpha, rho, lam, beta, mu_tab, theta, gamma,
                                w1, b1, w2, b2, sigma_list, mu_list,
                                prices, price_table, item_ids, itemset, userid,
                                (float*)d_out);
}

// round 13
// speedup vs baseline: 1.2200x; 1.0049x over previous
#include <cuda_runtime.h>
#include <math.h>
#include <stdint.h>

// Problem constants (fixed by the benchmark)
#define BB 64
#define TT 20
#define KK 50
#define EE 100
#define HH 64
#define NROWS (5*BB*KK + 2*BB)    // 16128 gathered rows
#define RROWS 32                  // rows per block in rows role
#define NBLK_ROWS (NROWS/RROWS)   // 504
#define NBLK_BASK (BB*10)         // 640: (b, t-pair), 8 warps

// block-role layout: producers first, then rows/basket strictly alternating
#define ROLE_A_BASE    0                   // 64 blocks
#define ROLE_RDA0_BASE (ROLE_A_BASE+BB)    // 64
#define ROLE_P_BASE    (ROLE_RDA0_BASE+BB) // 128
#define ROLE_KES_BASE  (ROLE_P_BASE+BB)    // 192
#define ROLE_MIX_BASE  (ROLE_KES_BASE+BB)  // 256
#define NTOT           (ROLE_MIX_BASE + NBLK_ROWS + NBLK_BASK) // 1400

// ---------------- scratch (no allocations allowed) ----------------
__device__ float g_A[BB*KK*KK];     // A[b,k,j] = alpha_c[k] . rho_c[j]
__device__ float g_rda0[BB*TT*KK];  // rho_c[j] . alpha_item0[t]
__device__ float g_P[BB*TT*KK];     // rho_item0[t] . alpha_c[k]
__device__ float g_ra00[BB*TT];     // rho_item0 . alpha_item0
__device__ float g_kesc[BB*KK];
__device__ float g_kes0[BB*TT];
__device__ float g_part_rows[NBLK_ROWS];
__device__ float g_part_bask[NBLK_BASK];
__device__ unsigned g_ready[BB];    // per-b producer count (4 expected); reset by last block
__device__ unsigned g_count;        // completion ticket; reset by last block

// order-preserving float<->int map (self-inverse)
__device__ __forceinline__ int f_ord(float f) {
    int i = __float_as_int(f);
    return i ^ ((i >> 31) & 0x7FFFFFFF);
}
__device__ __forceinline__ float ord_f(int i) {
    i ^= ((i >> 31) & 0x7FFFFFFF);
    return __int_as_float(i);
}

// =====================================================================
// One fused kernel: producers first; rows & basket interleaved by bid;
// role bodies identical to the validated 45.1us kernel (compact code).
// =====================================================================
__global__ void __launch_bounds__(256, 5) fused_kernel(
    const float* __restrict__ alpha, const float* __restrict__ rho,
    const float* __restrict__ lam,   const float* __restrict__ beta,
    const float* __restrict__ mu_tab,const float* __restrict__ theta,
    const float* __restrict__ gamma,
    const float* __restrict__ w1, const float* __restrict__ b1,
    const float* __restrict__ w2, const float* __restrict__ b2,
    const float* __restrict__ sigma, const float* __restrict__ mu,
    const float* __restrict__ prices, const float* __restrict__ price_table,
    const int* __restrict__ item_ids, const int* __restrict__ itemset,
    const int* __restrict__ userid, float* __restrict__ out)
{
    __shared__ __align__(16) char smem_raw[43008];
    __shared__ float ws[8];
    __shared__ double wd[8];
    __shared__ int is_last;
    const unsigned FULL = 0xffffffffu;
    int bx = blockIdx.x, tid = threadIdx.x;

    // role resolution for mixed region (strict alternation, then basket tail)
    int rows_idx = -1, bask_idx = -1;
    if (bx >= ROLE_MIX_BASE) {
        int i = bx - ROLE_MIX_BASE;
        if (i < 2*NBLK_ROWS) { if ((i & 1) == 0) rows_idx = i >> 1; else bask_idx = i >> 1; }
        else                 bask_idx = NBLK_ROWS + (i - 2*NBLK_ROWS);
    }

    if (bx < ROLE_RDA0_BASE) {
        // ============ A[b,k,j] Gram, 4x4 tiles ============
        int b = bx - ROLE_A_BASE;
        float* sA = (float*)smem_raw;      // [e][k] pitch 52
        float* sR = sA + EE*52;
        for (int i = tid; i < 2*EE; i += 256) { int e = i >> 1, k = 50 + (i & 1); sA[e*52+k]=0.f; sR[e*52+k]=0.f; }
        for (int i = tid; i < KK*EE; i += 256) {
            int k = i / EE, e = i - k*EE; int row = itemset[b*KK + k];
            sA[e*52 + k] = alpha[(size_t)row*EE + e];
            sR[e*52 + k] = rho  [(size_t)row*EE + e];
        }
        __syncthreads();
        if (tid < 169) {
            int ty = tid / 13, tx = tid - ty*13;
            float acc[4][4] = {};
            for (int e = 0; e < EE; e++) {
                float4 av = *(const float4*)&sA[e*52 + ty*4];
                float4 rv = *(const float4*)&sR[e*52 + tx*4];
                float aa[4] = {av.x, av.y, av.z, av.w};
                float rr[4] = {rv.x, rv.y, rv.z, rv.w};
                #pragma unroll
                for (int i = 0; i < 4; i++)
                    #pragma unroll
                    for (int j = 0; j < 4; j++) acc[i][j] = fmaf(aa[i], rr[j], acc[i][j]);
            }
            #pragma unroll
            for (int i = 0; i < 4; i++) {
                int k = ty*4 + i; if (k >= KK) break;
                #pragma unroll
                for (int j = 0; j < 4; j++) {
                    int jj = tx*4 + j;
                    if (jj < KK) g_A[(b*KK + k)*KK + jj] = acc[i][j];
                }
            }
        }
        __syncthreads();
        if (tid == 0) { __threadfence(); atomicAdd(&g_ready[b], 1u); }

    } else if (bx < ROLE_P_BASE) {
        // ============ rda0[b,t,j] = alpha_item0[t] . rho_c[j] ============
        int b = bx - ROLE_RDA0_BASE;
        float* sR  = (float*)smem_raw;     // [e][j] pitch 52
        float* sA0 = sR + EE*52;           // [e][t] pitch 20
        for (int i = tid; i < 2*EE; i += 256) { int e = i >> 1, k = 50 + (i & 1); sR[e*52+k]=0.f; }
        for (int i = tid; i < KK*EE; i += 256) {
            int k = i / EE, e = i - k*EE; int row = itemset[b*KK + k];
            sR[e*52 + k] = rho[(size_t)row*EE + e];
        }
        for (int i = tid; i < TT*EE; i += 256) {
            int t = i / EE, e = i - t*EE; int row = item_ids[b*TT + t];
            sA0[e*20 + t] = alpha[(size_t)row*EE + e];
        }
        __syncthreads();
        if (tid < 65) {
            int ty = tid / 13, tx = tid - ty*13;
            float acc[4][4] = {};
            for (int e = 0; e < EE; e++) {
                float4 av = *(const float4*)&sA0[e*20 + ty*4];
                float4 rv = *(const float4*)&sR[e*52 + tx*4];
                float aa[4] = {av.x, av.y, av.z, av.w};
                float rr[4] = {rv.x, rv.y, rv.z, rv.w};
                #pragma unroll
                for (int i = 0; i < 4; i++)
                    #pragma unroll
                    for (int j = 0; j < 4; j++) acc[i][j] = fmaf(aa[i], rr[j], acc[i][j]);
            }
            #pragma unroll
            for (int i = 0; i < 4; i++) {
                int t = ty*4 + i;
                #pragma unroll
                for (int j = 0; j < 4; j++) {
                    int jj = tx*4 + j;
                    if (jj < KK) g_rda0[(b*TT + t)*KK + jj] = acc[i][j];
                }
            }
        }
        __syncthreads();
        if (tid == 0) { __threadfence(); atomicAdd(&g_ready[b], 1u); }

    } else if (bx < ROLE_KES_BASE) {
        // ============ P[b,t,k] = rho_item0[t] . alpha_c[k]; ra00 ============
        int b = bx - ROLE_P_BASE;
        float* sAC = (float*)smem_raw;     // [e][k] pitch 52
        float* sR0 = sAC + EE*52;          // [e][t] pitch 20
        float* sA0 = sR0 + EE*20;
        for (int i = tid; i < 2*EE; i += 256) { int e = i >> 1, k = 50 + (i & 1); sAC[e*52+k]=0.f; }
        for (int i = tid; i < KK*EE; i += 256) {
            int k = i / EE, e = i - k*EE; int row = itemset[b*KK + k];
            sAC[e*52 + k] = alpha[(size_t)row*EE + e];
        }
        for (int i = tid; i < TT*EE; i += 256) {
            int t = i / EE, e = i - t*EE; int row = item_ids[b*TT + t];
            sR0[e*20 + t] = rho  [(size_t)row*EE + e];
            sA0[e*20 + t] = alpha[(size_t)row*EE + e];
        }
        __syncthreads();
        if (tid < 65) {
            int ty = tid / 13, tx = tid - ty*13;
            float acc[4][4] = {};
            for (int e = 0; e < EE; e++) {
                float4 rv = *(const float4*)&sR0[e*20 + ty*4];
                float4 av = *(const float4*)&sAC[e*52 + tx*4];
                float rr[4] = {rv.x, rv.y, rv.z, rv.w};
                float aa[4] = {av.x, av.y, av.z, av.w};
                #pragma unroll
                for (int i = 0; i < 4; i++)
                    #pragma unroll
                    for (int j = 0; j < 4; j++) acc[i][j] = fmaf(rr[i], aa[j], acc[i][j]);
            }
            #pragma unroll
            for (int i = 0; i < 4; i++) {
                int t = ty*4 + i;
                #pragma unroll
                for (int j = 0; j < 4; j++) {
                    int kk = tx*4 + j;
                    if (kk < KK) g_P[(b*TT + t)*KK + kk] = acc[i][j];
                }
            }
        }
        if (tid >= 96 && tid < 96 + TT) {
            int t = tid - 96;
            float s = 0.f;
            for (int e = 0; e < EE; e++) s = fmaf(sR0[e*20 + t], sA0[e*20 + t], s);
            g_ra00[b*TT + t] = s;
        }
        __syncthreads();
        if (tid == 0) { __threadfence(); atomicAdd(&g_ready[b], 1u); }

    } else if (bx < ROLE_MIX_BASE) {
        // ============ kes role, one block per b (70 entries, 8 warps) ============
        int b = bx - ROLE_KES_BASE;
        int w = tid >> 5, lane = tid & 31;
        int u = userid[b];
        const float* th = theta + (size_t)u*EE;
        const float* ga = gamma + (size_t)u*EE;
        float th0 = th[lane], th1 = th[32+lane], th2 = th[64+lane];
        float ga0 = ga[lane], ga1 = ga[32+lane], ga2 = ga[64+lane];
        float th3 = (lane < 4) ? th[96+lane] : 0.f;
        float ga3 = (lane < 4) ? ga[96+lane] : 0.f;

        for (int e = w; e < KK + TT; e += 8) {
            int idx; float price; bool is_c = (e < KK);
            if (is_c) { idx = itemset[b*KK + e]; price = price_table[idx]; }
            else      { int t = e - KK; idx = item_ids[b*TT + t]; price = prices[b*TT + t]; }
            const float* a  = alpha + (size_t)idx*EE;
            const float* l  = lam   + (size_t)idx*EE;
            const float* be = beta  + (size_t)idx*EE;
            float a0 = a[lane], a1 = a[32+lane], a2 = a[64+lane];
            float l0 = l[lane], l1 = l[32+lane], l2 = l[64+lane];
            float be0 = be[lane], be1 = be[32+lane], be2 = be[64+lane];
            float a3 = 0.f, l3 = 0.f, be3 = 0.f;
            if (lane < 4) { a3 = a[96+lane]; l3 = l[96+lane]; be3 = be[96+lane]; }

            float s1 = l0 + l1 + l2 + l3;
            float s2 = fmaf(th0,a0, fmaf(th1,a1, fmaf(th2,a2, th3*a3)));
            float s3 = fmaf(ga0,be0, fmaf(ga1,be1, fmaf(ga2,be2, ga3*be3)));
            #pragma unroll
            for (int o = 16; o; o >>= 1) {
                s1 += __shfl_xor_sync(FULL, s1, o);
                s2 += __shfl_xor_sync(FULL, s2, o);
                s3 += __shfl_xor_sync(FULL, s3, o);
            }
            if (lane == 0) {
                float val = (s1 + s2) * (1.f/EE) - (s3 * (1.f/EE)) * logf(price);
                if (is_c) g_kesc[b*KK + e] = val; else g_kes0[b*TT + (e - KK)] = val;
            }
        }
        __syncthreads();
        if (tid == 0) { __threadfence(); atomicAdd(&g_ready[b], 1u); }

    } else if (rows_idx >= 0) {
        // ============ rows role: Qf + prior over 32 gathered rows ============
        float* w1t   = (float*)smem_raw;        // [e][h] pitch 68
        float* v_rm  = w1t + EE*68;             // [row][e]
        float* ssrow = v_rm + RROWS*EE;
        float* w2s   = ssrow + RROWS;
        float* b1s   = w2s + HH;
        float* bsum  = b1s + HH;

        int base = rows_idx * RROWS;
        int g; const float* tab; int uoff = 0;
        if (base < 5*BB*KK) {
            g = base / (BB*KK);
            tab = (g==0)?alpha : (g==1)?rho : (g==2)?lam : (g==3)?beta : mu_tab;
        } else if (base < 5*BB*KK + BB) { g = 5; tab = theta; uoff = base - 5*BB*KK; }
        else                            { g = 6; tab = gamma; uoff = base - 5*BB*KK - BB; }
        float sg = sigma[g], muv = mu[g];
        float b2v = b2[0];

        for (int i = tid; i < HH*EE; i += 256) {
            int h = i / EE, e = i - h*EE;
            w1t[e*68 + h] = w1[i];
        }
        if (tid < HH) { w2s[tid] = w2[tid]; b1s[tid] = b1[tid]; }
        if (tid == 0) *bsum = 0.f;

        for (int i = tid; i < RROWS*EE; i += 256) {
            int rl = i / EE, e = i - rl*EE;
            int idx;
            if (g < 5) idx = itemset[base - g*(BB*KK) + rl];
            else       idx = userid[uoff + rl];
            v_rm[rl*EE + e] = tab[(size_t)idx*EE + e];
        }
        __syncthreads();

        if (tid < RROWS) {
            float ss = 0.f;
            for (int e = 0; e < EE; e++) { float x = v_rm[tid*EE + e] - muv; ss = fmaf(x, x, ss); }
            ssrow[tid] = ss;
        }

        int ty = tid >> 4, tx = tid & 15;
        float acc[2][4];
        #pragma unroll
        for (int i = 0; i < 2; i++)
            #pragma unroll
            for (int j = 0; j < 4; j++) acc[i][j] = b1s[tx*4 + j];

        for (int e = 0; e < EE; e++) {
            float4 wv = *(const float4*)&w1t[e*68 + tx*4];
            float vv0 = v_rm[(2*ty + 0)*EE + e];
            float vv1 = v_rm[(2*ty + 1)*EE + e];
            acc[0][0] = fmaf(vv0, wv.x, acc[0][0]);
            acc[0][1] = fmaf(vv0, wv.y, acc[0][1]);
            acc[0][2] = fmaf(vv0, wv.z, acc[0][2]);
            acc[0][3] = fmaf(vv0, wv.w, acc[0][3]);
            acc[1][0] = fmaf(vv1, wv.x, acc[1][0]);
            acc[1][1] = fmaf(vv1, wv.y, acc[1][1]);
            acc[1][2] = fmaf(vv1, wv.z, acc[1][2]);
            acc[1][3] = fmaf(vv1, wv.w, acc[1][3]);
        }

        float z[2];
        #pragma unroll
        for (int i = 0; i < 2; i++) {
            float s = 0.f;
            #pragma unroll
            for (int j = 0; j < 4; j++) s = fmaf(fmaxf(acc[i][j], 0.f), w2s[tx*4 + j], s);
            z[i] = s;
        }
        #pragma unroll
        for (int o = 8; o; o >>= 1) {
            z[0] += __shfl_xor_sync(FULL, z[0], o);
            z[1] += __shfl_xor_sync(FULL, z[1], o);
        }
        __syncthreads();
        if (tx == 0) {
            float local = 0.f;
            #pragma unroll
            for (int i = 0; i < 2; i++) {
                float q = 1.f / (1.f + expf(-(z[i] + b2v)));
                local += (-0.5f/sg)*ssrow[2*ty + i] - q;
            }
            atomicAdd(bsum, local);
        }
        __syncthreads();
        if (tid == 0) g_part_rows[rows_idx] = *bsum;

    } else {
        // ============ basket role: 2 t's x 4 k-chunks per block ============
        int bx2 = bask_idx;                 // 0..639
        int b = bx2 / 10, pair = bx2 % 10;
        int w = tid >> 5, lane = tid & 31;
        int sub = w >> 2, chunk = w & 3;
        int t = pair*2 + sub;
        int bt = b*TT + t;
        int base = b*KK;
        // balanced chunk bounds by cost KS + 3*(KE-KS): {0,21,35,44,50}
        int kstart = (chunk==0) ? 0  : (chunk==1) ? 21 : (chunk==2) ? 35 : 44;
        int kend   = (chunk==0) ? 21 : (chunk==1) ? 35 : (chunk==2) ? 44 : 50;

        // inputs not produced in-kernel can be read pre-wait
        int item0 = item_ids[bt];
        bool v1 = (lane < KK - 32);
        int c0i = itemset[base + lane];
        int c1i = v1 ? itemset[base + 32 + lane] : 0;
        bool mj0 = (c0i != item0);
        bool mj1 = v1 && (c1i != item0);
        unsigned ball0 = __ballot_sync(FULL, mj0);
        unsigned ball1 = __ballot_sync(FULL, mj1);
        int popA = __popc(ball0);

        // wait for this b's producers (A, rda0, P, kes)
        if (tid == 0) {
            volatile unsigned* f = &g_ready[b];
            while (*f < 4u) __nanosleep(64);
        }
        __syncthreads();
        __threadfence();

        float* sA = (float*)smem_raw;       // A[b] [k][j], 10KB
        for (int i = tid; i < KK*KK; i += 256) sA[i] = g_A[base*KK + i];

        float kesc0 = g_kesc[base + lane];
        float kesc1 = v1 ? g_kesc[base + 32 + lane] : 0.f;
        float rj0 = g_rda0[bt*KK + lane];
        float rj1 = v1 ? g_rda0[bt*KK + 32 + lane] : 0.f;
        float ra00  = g_ra00[bt];
        float kes0v = g_kes0[bt];

        // one-time masked inclusive prefix scan of P over k (two 32-halves)
        float px0 = mj0 ? g_P[bt*KK + lane] : 0.f;
        float px1 = mj1 ? g_P[bt*KK + 32 + lane] : 0.f;
        #pragma unroll
        for (int d = 1; d < 32; d <<= 1) {
            float v = __shfl_up_sync(FULL, px0, d);
            if (lane >= d) px0 += v;
        }
        float tot0 = __shfl_sync(FULL, px0, 31);
        #pragma unroll
        for (int d = 1; d < 32; d <<= 1) {
            float v = __shfl_up_sync(FULL, px1, d);
            if (lane >= d) px1 += v;
        }
        px1 += tot0;

        __syncthreads();   // sA ready

        // chunk base: Cj up to kstart (cheap pipelined masked FMAs)
        float Cj0 = 0.f, Cj1 = 0.f, acc = 0.f;
        for (int k = 0; k < kstart; k++) {
            float mf = ((k < 32 ? (ball0 >> k) : (ball1 >> (k-32))) & 1u) ? 1.f : 0.f;
            Cj0 = fmaf(mf, sA[k*KK + lane], Cj0);
            if (v1) Cj1 = fmaf(mf, sA[k*KK + 32 + lane], Cj1);
        }
        // running count of set bits strictly below kstart
        int cnt;
        if (kstart == 0)        cnt = 0;
        else if (kstart <= 32)  cnt = __popc(ball0 & ((1u << kstart) - 1u));
        else                    cnt = popA + __popc(ball1 & ((1u << (kstart-32)) - 1u));

        for (int k = kstart; k < kend; k++) {
            bool mk = ((k < 32 ? (ball0 >> k) : (ball1 >> (k-32))) & 1u);
            if (mk) {   // uniform branch; when item0 == c_k the step is a no-op
                cnt++;
                float ak0 = sA[k*KK + lane];
                float ak1 = v1 ? sA[k*KK + 32 + lane] : 0.f;
                Cj0 += ak0;
                Cj1 += ak1;

                float lenk   = 1.f + (float)cnt;
                float rdenom = __fdividef(1.f, (lenk + 1.f) * (float)EE);

                float c0 = -INFINITY, cc = -INFINITY;
                if (mj0 && lane > k) {
                    float bs = rj0 + Cj0;
                    c0 = fmaf(bs + rj0, rdenom, kesc0);
                    cc = fmaf(bs + ak0, rdenom, kesc0);
                }
                if (mj1 && (lane + 32) > k) {
                    float bs = rj1 + Cj1;
                    float y0 = fmaf(bs + rj1, rdenom, kesc1);
                    float yc = fmaf(bs + ak1, rdenom, kesc1);
                    c0 = fmaxf(c0, y0); cc = fmaxf(cc, yc);
                }

                int m0i = __reduce_max_sync(FULL, f_ord(c0));
                int mci = __reduce_max_sync(FULL, f_ord(cc));

                if (lane == (k & 31)) {     // designated j==k; mjd == mk == true here
                    float m0 = ord_f(m0i);
                    float mc = ord_f(mci);
                    float kescd = (k < 32) ? kesc0 : kesc1;
                    float rjd   = (k < 32) ? rj0   : rj1;
                    float Cjd   = (k < 32) ? Cj0   : Cj1;
                    float Pcd   = (k < 32) ? px0   : px1;
                    float inv = __fdividef(1.f, (float)EE * lenk);
                    float i0v = (ra00 + Pcd) * inv;
                    float icv = (rjd  + Cjd) * inv;
                    float Kes0 = kes0v + i0v + fmaxf(0.f, m0);
                    float KesC = kescd + icv + fmaxf(0.f, mc);
                    float xq = Kes0 - KesC;
                    acc += fminf(xq, 0.f) - log1pf(expf(-fabsf(xq)));
                }
            }
        }

        #pragma unroll
        for (int o = 16; o; o >>= 1) acc += __shfl_xor_sync(FULL, acc, o);
        if (lane == 0) ws[w] = acc;
        __syncthreads();
        if (tid == 0) {
            float s = 0.f;
            #pragma unroll
            for (int i = 0; i < 8; i++) s += ws[i];
            g_part_bask[bx2] = s;
        }
    }

    // ================= common epilogue: completion ticket =================
    __syncthreads();
    if (tid == 0) {
        __threadfence();
        unsigned tk = atomicAdd(&g_count, 1u);
        is_last = (tk == NTOT - 1) ? 1 : 0;
    }
    __syncthreads();

    if (is_last) {
        __threadfence();  // see all blocks' partial stores
        double s = 0.0;
        for (int i = tid; i < NBLK_ROWS; i += 256) s += (double)g_part_rows[i];
        for (int i = tid; i < NBLK_BASK; i += 256) s += (double)g_part_bask[i];
        #pragma unroll
        for (int o = 16; o; o >>= 1) s += __shfl_xor_sync(FULL, s, o);
        if ((tid & 31) == 0) wd[tid >> 5] = s;
        __syncthreads();
        if (tid == 0) {
            double tt = 0.0;
            #pragma unroll
            for (int i = 0; i < 8; i++) tt += wd[i];
            out[0] = (float)tt;
            g_count = 0u;                       // reset for next replay
        }
        if (tid < BB) g_ready[tid] = 0u;        // reset flags for next replay
    }
}

// ================= launch: ONE node, no driver objects ================
extern "C" void kernel_launch(void* const* d_in, const int* in_sizes, int n_in,
                              void* d_out, int out_size)
{
    const float* alpha       = (const float*)d_in[0];
    const float* rho         = (const float*)d_in[1];
    const float* lam         = (const float*)d_in[2];
    const float* beta        = (const float*)d_in[3];
    const float* mu_tab      = (const float*)d_in[4];
    const float* theta       = (const float*)d_in[5];
    const float* gamma       = (const float*)d_in[6];
    const float* w1          = (const float*)d_in[7];
    const float* b1          = (const float*)d_in[8];
    const float* w2          = (const float*)d_in[9];
    const float* b2          = (const float*)d_in[10];
    const float* sigma_list  = (const float*)d_in[11];
    const float* mu_list     = (const float*)d_in[12];
    const float* prices      = (const float*)d_in[13];
    const float* price_table = (const float*)d_in[14];
    const int*   item_ids    = (const int*)d_in[15];
    const int*   itemset     = (const int*)d_in[16];
    const int*   userid      = (const int*)d_in[17];

    fused_kernel<<<NTOT, 256>>>(alpha, rho, lam, beta, mu_tab, theta, gamma,
                                w1, b1, w2, b2, sigma_list, mu_list,
                                prices, price_table, item_ids, itemset, userid,
                                (float*)d_out);
}

// round 14
// speedup vs baseline: 1.2243x; 1.0035x over previous
#include <cuda_runtime.h>
#include <math.h>
#include <stdint.h>

// Problem constants (fixed by the benchmark)
#define BB 64
#define TT 20
#define KK 50
#define EE 100
#define HH 64
#define NROWS (5*BB*KK + 2*BB)    // 16128 gathered rows
#define RROWS 32                  // rows per block in rows role
#define NBLK_ROWS (NROWS/RROWS)   // 504
#define NBLK_BASK (BB*10)         // 640: (b, t-pair), 8 warps

// block-role layout: producers first, then rows/basket strictly alternating
#define ROLE_A_BASE    0                   // 64 blocks
#define ROLE_RDA0_BASE (ROLE_A_BASE+BB)    // 64
#define ROLE_P_BASE    (ROLE_RDA0_BASE+BB) // 128
#define ROLE_KES_BASE  (ROLE_P_BASE+BB)    // 192
#define ROLE_MIX_BASE  (ROLE_KES_BASE+BB)  // 256
#define NTOT           (ROLE_MIX_BASE + NBLK_ROWS + NBLK_BASK) // 1400

// ---------------- scratch (no allocations allowed) ----------------
__device__ float g_A[BB*KK*KK];     // A[b,k,j] = alpha_c[k] . rho_c[j]
__device__ float g_rda0[BB*TT*KK];  // rho_c[j] . alpha_item0[t]
__device__ float g_P[BB*TT*KK];     // rho_item0[t] . alpha_c[k]
__device__ float g_ra00[BB*TT];     // rho_item0 . alpha_item0
__device__ float g_kesc[BB*KK];
__device__ float g_kes0[BB*TT];
__device__ float g_part_rows[NBLK_ROWS];
__device__ float g_part_bask[NBLK_BASK];
__device__ unsigned g_ready[BB];    // per-b producer count (4 expected); reset by last block
__device__ unsigned g_count;        // completion ticket; reset by last block

// order-preserving float<->int map (self-inverse)
__device__ __forceinline__ int f_ord(float f) {
    int i = __float_as_int(f);
    return i ^ ((i >> 31) & 0x7FFFFFFF);
}
__device__ __forceinline__ float ord_f(int i) {
    i ^= ((i >> 31) & 0x7FFFFFFF);
    return __int_as_float(i);
}

// =====================================================================
// One fused kernel: producers first; rows & basket interleaved by bid;
// role bodies identical to the validated 45.1us kernel (compact code).
// =====================================================================
__global__ void __launch_bounds__(256, 5) fused_kernel(
    const float* __restrict__ alpha, const float* __restrict__ rho,
    const float* __restrict__ lam,   const float* __restrict__ beta,
    const float* __restrict__ mu_tab,const float* __restrict__ theta,
    const float* __restrict__ gamma,
    const float* __restrict__ w1, const float* __restrict__ b1,
    const float* __restrict__ w2, const float* __restrict__ b2,
    const float* __restrict__ sigma, const float* __restrict__ mu,
    const float* __restrict__ prices, const float* __restrict__ price_table,
    const int* __restrict__ item_ids, const int* __restrict__ itemset,
    const int* __restrict__ userid, float* __restrict__ out)
{
    __shared__ __align__(16) char smem_raw[43008];
    __shared__ float ws[8];
    __shared__ double wd[8];
    __shared__ int is_last;
    const unsigned FULL = 0xffffffffu;
    int bx = blockIdx.x, tid = threadIdx.x;

    // role resolution for mixed region (strict alternation, then basket tail)
    int rows_idx = -1, bask_idx = -1;
    if (bx >= ROLE_MIX_BASE) {
        int i = bx - ROLE_MIX_BASE;
        if (i < 2*NBLK_ROWS) { if ((i & 1) == 0) rows_idx = i >> 1; else bask_idx = i >> 1; }
        else                 bask_idx = NBLK_ROWS + (i - 2*NBLK_ROWS);
    }

    if (bx < ROLE_RDA0_BASE) {
        // ============ A[b,k,j] Gram, 4x4 tiles ============
        int b = bx - ROLE_A_BASE;
        float* sA = (float*)smem_raw;      // [e][k] pitch 52
        float* sR = sA + EE*52;
        for (int i = tid; i < 2*EE; i += 256) { int e = i >> 1, k = 50 + (i & 1); sA[e*52+k]=0.f; sR[e*52+k]=0.f; }
        for (int i = tid; i < KK*EE; i += 256) {
            int k = i / EE, e = i - k*EE; int row = itemset[b*KK + k];
            sA[e*52 + k] = alpha[(size_t)row*EE + e];
            sR[e*52 + k] = rho  [(size_t)row*EE + e];
        }
        __syncthreads();
        if (tid < 169) {
            int ty = tid / 13, tx = tid - ty*13;
            float acc[4][4] = {};
            for (int e = 0; e < EE; e++) {
                float4 av = *(const float4*)&sA[e*52 + ty*4];
                float4 rv = *(const float4*)&sR[e*52 + tx*4];
                float aa[4] = {av.x, av.y, av.z, av.w};
                float rr[4] = {rv.x, rv.y, rv.z, rv.w};
                #pragma unroll
                for (int i = 0; i < 4; i++)
                    #pragma unroll
                    for (int j = 0; j < 4; j++) acc[i][j] = fmaf(aa[i], rr[j], acc[i][j]);
            }
            #pragma unroll
            for (int i = 0; i < 4; i++) {
                int k = ty*4 + i; if (k >= KK) break;
                #pragma unroll
                for (int j = 0; j < 4; j++) {
                    int jj = tx*4 + j;
                    if (jj < KK) g_A[(b*KK + k)*KK + jj] = acc[i][j];
                }
            }
        }
        __syncthreads();
        if (tid == 0) { __threadfence(); atomicAdd(&g_ready[b], 1u); }

    } else if (bx < ROLE_P_BASE) {
        // ============ rda0[b,t,j] = alpha_item0[t] . rho_c[j] ============
        int b = bx - ROLE_RDA0_BASE;
        float* sR  = (float*)smem_raw;     // [e][j] pitch 52
        float* sA0 = sR + EE*52;           // [e][t] pitch 20
        for (int i = tid; i < 2*EE; i += 256) { int e = i >> 1, k = 50 + (i & 1); sR[e*52+k]=0.f; }
        for (int i = tid; i < KK*EE; i += 256) {
            int k = i / EE, e = i - k*EE; int row = itemset[b*KK + k];
            sR[e*52 + k] = rho[(size_t)row*EE + e];
        }
        for (int i = tid; i < TT*EE; i += 256) {
            int t = i / EE, e = i - t*EE; int row = item_ids[b*TT + t];
            sA0[e*20 + t] = alpha[(size_t)row*EE + e];
        }
        __syncthreads();
        if (tid < 65) {
            int ty = tid / 13, tx = tid - ty*13;
            float acc[4][4] = {};
            for (int e = 0; e < EE; e++) {
                float4 av = *(const float4*)&sA0[e*20 + ty*4];
                float4 rv = *(const float4*)&sR[e*52 + tx*4];
                float aa[4] = {av.x, av.y, av.z, av.w};
                float rr[4] = {rv.x, rv.y, rv.z, rv.w};
                #pragma unroll
                for (int i = 0; i < 4; i++)
                    #pragma unroll
                    for (int j = 0; j < 4; j++) acc[i][j] = fmaf(aa[i], rr[j], acc[i][j]);
            }
            #pragma unroll
            for (int i = 0; i < 4; i++) {
                int t = ty*4 + i;
                #pragma unroll
                for (int j = 0; j < 4; j++) {
                    int jj = tx*4 + j;
                    if (jj < KK) g_rda0[(b*TT + t)*KK + jj] = acc[i][j];
                }
            }
        }
        __syncthreads();
        if (tid == 0) { __threadfence(); atomicAdd(&g_ready[b], 1u); }

    } else if (bx < ROLE_KES_BASE) {
        // ============ P[b,t,k] = rho_item0[t] . alpha_c[k]; ra00 ============
        int b = bx - ROLE_P_BASE;
        float* sAC = (float*)smem_raw;     // [e][k] pitch 52
        float* sR0 = sAC + EE*52;          // [e][t] pitch 20
        float* sA0 = sR0 + EE*20;
        for (int i = tid; i < 2*EE; i += 256) { int e = i >> 1, k = 50 + (i & 1); sAC[e*52+k]=0.f; }
        for (int i = tid; i < KK*EE; i += 256) {
            int k = i / EE, e = i - k*EE; int row = itemset[b*KK + k];
            sAC[e*52 + k] = alpha[(size_t)row*EE + e];
        }
        for (int i = tid; i < TT*EE; i += 256) {
            int t = i / EE, e = i - t*EE; int row = item_ids[b*TT + t];
            sR0[e*20 + t] = rho  [(size_t)row*EE + e];
            sA0[e*20 + t] = alpha[(size_t)row*EE + e];
        }
        __syncthreads();
        if (tid < 65) {
            int ty = tid / 13, tx = tid - ty*13;
            float acc[4][4] = {};
            for (int e = 0; e < EE; e++) {
                float4 rv = *(const float4*)&sR0[e*20 + ty*4];
                float4 av = *(const float4*)&sAC[e*52 + tx*4];
                float rr[4] = {rv.x, rv.y, rv.z, rv.w};
                float aa[4] = {av.x, av.y, av.z, av.w};
                #pragma unroll
                for (int i = 0; i < 4; i++)
                    #pragma unroll
                    for (int j = 0; j < 4; j++) acc[i][j] = fmaf(rr[i], aa[j], acc[i][j]);
            }
            #pragma unroll
            for (int i = 0; i < 4; i++) {
                int t = ty*4 + i;
                #pragma unroll
                for (int j = 0; j < 4; j++) {
                    int kk = tx*4 + j;
                    if (kk < KK) g_P[(b*TT + t)*KK + kk] = acc[i][j];
                }
            }
        }
        if (tid >= 96 && tid < 96 + TT) {
            int t = tid - 96;
            float s = 0.f;
            for (int e = 0; e < EE; e++) s = fmaf(sR0[e*20 + t], sA0[e*20 + t], s);
            g_ra00[b*TT + t] = s;
        }
        __syncthreads();
        if (tid == 0) { __threadfence(); atomicAdd(&g_ready[b], 1u); }

    } else if (bx < ROLE_MIX_BASE) {
        // ============ kes role, one block per b (70 entries, 8 warps) ============
        int b = bx - ROLE_KES_BASE;
        int w = tid >> 5, lane = tid & 31;
        int u = userid[b];
        const float* th = theta + (size_t)u*EE;
        const float* ga = gamma + (size_t)u*EE;
        float th0 = th[lane], th1 = th[32+lane], th2 = th[64+lane];
        float ga0 = ga[lane], ga1 = ga[32+lane], ga2 = ga[64+lane];
        float th3 = (lane < 4) ? th[96+lane] : 0.f;
        float ga3 = (lane < 4) ? ga[96+lane] : 0.f;

        for (int e = w; e < KK + TT; e += 8) {
            int idx; float price; bool is_c = (e < KK);
            if (is_c) { idx = itemset[b*KK + e]; price = price_table[idx]; }
            else      { int t = e - KK; idx = item_ids[b*TT + t]; price = prices[b*TT + t]; }
            const float* a  = alpha + (size_t)idx*EE;
            const float* l  = lam   + (size_t)idx*EE;
            const float* be = beta  + (size_t)idx*EE;
            float a0 = a[lane], a1 = a[32+lane], a2 = a[64+lane];
            float l0 = l[lane], l1 = l[32+lane], l2 = l[64+lane];
            float be0 = be[lane], be1 = be[32+lane], be2 = be[64+lane];
            float a3 = 0.f, l3 = 0.f, be3 = 0.f;
            if (lane < 4) { a3 = a[96+lane]; l3 = l[96+lane]; be3 = be[96+lane]; }

            float s1 = l0 + l1 + l2 + l3;
            float s2 = fmaf(th0,a0, fmaf(th1,a1, fmaf(th2,a2, th3*a3)));
            float s3 = fmaf(ga0,be0, fmaf(ga1,be1, fmaf(ga2,be2, ga3*be3)));
            #pragma unroll
            for (int o = 16; o; o >>= 1) {
                s1 += __shfl_xor_sync(FULL, s1, o);
                s2 += __shfl_xor_sync(FULL, s2, o);
                s3 += __shfl_xor_sync(FULL, s3, o);
            }
            if (lane == 0) {
                float val = (s1 + s2) * (1.f/EE) - (s3 * (1.f/EE)) * logf(price);
                if (is_c) g_kesc[b*KK + e] = val; else g_kes0[b*TT + (e - KK)] = val;
            }
        }
        __syncthreads();
        if (tid == 0) { __threadfence(); atomicAdd(&g_ready[b], 1u); }

    } else if (rows_idx >= 0) {
        // ============ rows role: Qf + prior over 32 gathered rows ============
        float* w1t   = (float*)smem_raw;        // [e][h] pitch 68
        float* v_rm  = w1t + EE*68;             // [row][e]
        float* ssrow = v_rm + RROWS*EE;
        float* w2s   = ssrow + RROWS;
        float* b1s   = w2s + HH;
        float* bsum  = b1s + HH;

        int base = rows_idx * RROWS;
        int g; const float* tab; int uoff = 0;
        if (base < 5*BB*KK) {
            g = base / (BB*KK);
            tab = (g==0)?alpha : (g==1)?rho : (g==2)?lam : (g==3)?beta : mu_tab;
        } else if (base < 5*BB*KK + BB) { g = 5; tab = theta; uoff = base - 5*BB*KK; }
        else                            { g = 6; tab = gamma; uoff = base - 5*BB*KK - BB; }
        float sg = sigma[g], muv = mu[g];
        float b2v = b2[0];

        for (int i = tid; i < HH*EE; i += 256) {
            int h = i / EE, e = i - h*EE;
            w1t[e*68 + h] = w1[i];
        }
        if (tid < HH) { w2s[tid] = w2[tid]; b1s[tid] = b1[tid]; }
        if (tid == 0) *bsum = 0.f;

        for (int i = tid; i < RROWS*EE; i += 256) {
            int rl = i / EE, e = i - rl*EE;
            int idx;
            if (g < 5) idx = itemset[base - g*(BB*KK) + rl];
            else       idx = userid[uoff + rl];
            v_rm[rl*EE + e] = tab[(size_t)idx*EE + e];
        }
        __syncthreads();

        if (tid < RROWS) {
            float ss = 0.f;
            for (int e = 0; e < EE; e++) { float x = v_rm[tid*EE + e] - muv; ss = fmaf(x, x, ss); }
            ssrow[tid] = ss;
        }

        int ty = tid >> 4, tx = tid & 15;
        float acc[2][4];
        #pragma unroll
        for (int i = 0; i < 2; i++)
            #pragma unroll
            for (int j = 0; j < 4; j++) acc[i][j] = b1s[tx*4 + j];

        for (int e = 0; e < EE; e++) {
            float4 wv = *(const float4*)&w1t[e*68 + tx*4];
            float vv0 = v_rm[(2*ty + 0)*EE + e];
            float vv1 = v_rm[(2*ty + 1)*EE + e];
            acc[0][0] = fmaf(vv0, wv.x, acc[0][0]);
            acc[0][1] = fmaf(vv0, wv.y, acc[0][1]);
            acc[0][2] = fmaf(vv0, wv.z, acc[0][2]);
            acc[0][3] = fmaf(vv0, wv.w, acc[0][3]);
            acc[1][0] = fmaf(vv1, wv.x, acc[1][0]);
            acc[1][1] = fmaf(vv1, wv.y, acc[1][1]);
            acc[1][2] = fmaf(vv1, wv.z, acc[1][2]);
            acc[1][3] = fmaf(vv1, wv.w, acc[1][3]);
        }

        float z[2];
        #pragma unroll
        for (int i = 0; i < 2; i++) {
            float s = 0.f;
            #pragma unroll
            for (int j = 0; j < 4; j++) s = fmaf(fmaxf(acc[i][j], 0.f), w2s[tx*4 + j], s);
            z[i] = s;
        }
        #pragma unroll
        for (int o = 8; o; o >>= 1) {
            z[0] += __shfl_xor_sync(FULL, z[0], o);
            z[1] += __shfl_xor_sync(FULL, z[1], o);
        }
        __syncthreads();
        if (tx == 0) {
            float local = 0.f;
            #pragma unroll
            for (int i = 0; i < 2; i++) {
                float q = 1.f / (1.f + expf(-(z[i] + b2v)));
                local += (-0.5f/sg)*ssrow[2*ty + i] - q;
            }
            atomicAdd(bsum, local);
        }
        __syncthreads();
        if (tid == 0) g_part_rows[rows_idx] = *bsum;

    } else {
        // ============ basket role: 2 t's x 4 k-chunks per block ============
        int bx2 = bask_idx;                 // 0..639
        int b = bx2 / 10, pair = bx2 % 10;
        int w = tid >> 5, lane = tid & 31;
        int sub = w >> 2, chunk = w & 3;
        int t = pair*2 + sub;
        int bt = b*TT + t;
        int base = b*KK;
        // balanced chunk bounds by cost KS + 3*(KE-KS): {0,21,35,44,50}
        int kstart = (chunk==0) ? 0  : (chunk==1) ? 21 : (chunk==2) ? 35 : 44;
        int kend   = (chunk==0) ? 21 : (chunk==1) ? 35 : (chunk==2) ? 44 : 50;

        // inputs not produced in-kernel can be read pre-wait
        int item0 = item_ids[bt];
        bool v1 = (lane < KK - 32);
        int c0i = itemset[base + lane];
        int c1i = v1 ? itemset[base + 32 + lane] : 0;
        bool mj0 = (c0i != item0);
        bool mj1 = v1 && (c1i != item0);
        unsigned ball0 = __ballot_sync(FULL, mj0);
        unsigned ball1 = __ballot_sync(FULL, mj1);
        int popA = __popc(ball0);

        // wait for this b's producers (A, rda0, P, kes)
        if (tid == 0) {
            volatile unsigned* f = &g_ready[b];
            while (*f < 4u) __nanosleep(64);
        }
        __syncthreads();
        __threadfence();

        float* sA = (float*)smem_raw;       // A[b] [k][j], 10KB
        for (int i = tid; i < KK*KK; i += 256) sA[i] = g_A[base*KK + i];

        float kesc0 = g_kesc[base + lane];
        float kesc1 = v1 ? g_kesc[base + 32 + lane] : 0.f;
        float rj0 = g_rda0[bt*KK + lane];
        float rj1 = v1 ? g_rda0[bt*KK + 32 + lane] : 0.f;
        float ra00  = g_ra00[bt];
        float kes0v = g_kes0[bt];

        // one-time masked inclusive prefix scan of P over k (two 32-halves)
        float px0 = mj0 ? g_P[bt*KK + lane] : 0.f;
        float px1 = mj1 ? g_P[bt*KK + 32 + lane] : 0.f;
        #pragma unroll
        for (int d = 1; d < 32; d <<= 1) {
            float v = __shfl_up_sync(FULL, px0, d);
            if (lane >= d) px0 += v;
        }
        float tot0 = __shfl_sync(FULL, px0, 31);
        #pragma unroll
        for (int d = 1; d < 32; d <<= 1) {
            float v = __shfl_up_sync(FULL, px1, d);
            if (lane >= d) px1 += v;
        }
        px1 += tot0;

        __syncthreads();   // sA ready

        // chunk base: Cj up to kstart (cheap pipelined masked FMAs)
        float Cj0 = 0.f, Cj1 = 0.f, acc = 0.f;
        for (int k = 0; k < kstart; k++) {
            float mf = ((k < 32 ? (ball0 >> k) : (ball1 >> (k-32))) & 1u) ? 1.f : 0.f;
            Cj0 = fmaf(mf, sA[k*KK + lane], Cj0);
            if (v1) Cj1 = fmaf(mf, sA[k*KK + 32 + lane], Cj1);
        }
        // running count of set bits strictly below kstart
        int cnt;
        if (kstart == 0)        cnt = 0;
        else if (kstart <= 32)  cnt = __popc(ball0 & ((1u << kstart) - 1u));
        else                    cnt = popA + __popc(ball1 & ((1u << (kstart-32)) - 1u));

        for (int k = kstart; k < kend; k++) {
            bool mk = ((k < 32 ? (ball0 >> k) : (ball1 >> (k-32))) & 1u);
            if (mk) {   // uniform branch; when item0 == c_k the step is a no-op
                cnt++;
                float ak0 = sA[k*KK + lane];
                float ak1 = v1 ? sA[k*KK + 32 + lane] : 0.f;
                Cj0 += ak0;
                Cj1 += ak1;

                float lenk   = 1.f + (float)cnt;
                float rdenom = __fdividef(1.f, (lenk + 1.f) * (float)EE);

                float c0 = -INFINITY, cc = -INFINITY;
                if (mj0 && lane > k) {
                    float bs = rj0 + Cj0;
                    c0 = fmaf(bs + rj0, rdenom, kesc0);
                    cc = fmaf(bs + ak0, rdenom, kesc0);
                }
                if (mj1 && (lane + 32) > k) {
                    float bs = rj1 + Cj1;
                    float y0 = fmaf(bs + rj1, rdenom, kesc1);
                    float yc = fmaf(bs + ak1, rdenom, kesc1);
                    c0 = fmaxf(c0, y0); cc = fmaxf(cc, yc);
                }

                int m0i = __reduce_max_sync(FULL, f_ord(c0));
                int mci = __reduce_max_sync(FULL, f_ord(cc));

                if (lane == (k & 31)) {     // designated j==k; mjd == mk == true here
                    float m0 = ord_f(m0i);
                    float mc = ord_f(mci);
                    float kescd = (k < 32) ? kesc0 : kesc1;
                    float rjd   = (k < 32) ? rj0   : rj1;
                    float Cjd   = (k < 32) ? Cj0   : Cj1;
                    float Pcd   = (k < 32) ? px0   : px1;
                    float inv = __fdividef(1.f, (float)EE * lenk);
                    float i0v = (ra00 + Pcd) * inv;
                    float icv = (rjd  + Cjd) * inv;
                    float Kes0 = kes0v + i0v + fmaxf(0.f, m0);
                    float KesC = kescd + icv + fmaxf(0.f, mc);
                    float xq = Kes0 - KesC;
                    acc += fminf(xq, 0.f) - log1pf(expf(-fabsf(xq)));
                }
            }
        }

        #pragma unroll
        for (int o = 16; o; o >>= 1) acc += __shfl_xor_sync(FULL, acc, o);
        if (lane == 0) ws[w] = acc;
        __syncthreads();
        if (tid == 0) {
            float s = 0.f;
            #pragma unroll
            for (int i = 0; i < 8; i++) s += ws[i];
            g_part_bask[bx2] = s;
        }
    }

    // ================= common epilogue: completion ticket =================
    __syncthreads();
    if (tid == 0) {
        __threadfence();
        unsigned tk = atomicAdd(&g_count, 1u);
        is_last = (tk == NTOT - 1) ? 1 : 0;
    }
    __syncthreads();

    if (is_last) {
        __threadfence();  // see all blocks' partial stores
        double s = 0.0;
        for (int i = tid; i < NBLK_ROWS; i += 256) s += (double)g_part_rows[i];
        for (int i = tid; i < NBLK_BASK; i += 256) s += (double)g_part_bask[i];
        #pragma unroll
        for (int o = 16; o; o >>= 1) s += __shfl_xor_sync(FULL, s, o);
        if ((tid & 31) == 0) wd[tid >> 5] = s;
        __syncthreads();
        if (tid == 0) {
            double tt = 0.0;
            #pragma unroll
            for (int i = 0; i < 8; i++) tt += wd[i];
            out[0] = (float)tt;
            g_count = 0u;                       // reset for next replay
        }
        if (tid < BB) g_ready[tid] = 0u;        // reset flags for next replay
    }
}

// ================= launch: ONE node, no driver objects ================
extern "C" void kernel_launch(void* const* d_in, const int* in_sizes, int n_in,
                              void* d_out, int out_size)
{
    const float* alpha       = (const float*)d_in[0];
    const float* rho         = (const float*)d_in[1];
    const float* lam         = (const float*)d_in[2];
    const float* beta        = (const float*)d_in[3];
    const float* mu_tab      = (const float*)d_in[4];
    const float* theta       = (const float*)d_in[5];
    const float* gamma       = (const float*)d_in[6];
    const float* w1          = (const float*)d_in[7];
    const float* b1          = (const float*)d_in[8];
    const float* w2          = (const float*)d_in[9];
    const float* b2          = (const float*)d_in[10];
    const float* sigma_list  = (const float*)d_in[11];
    const float* mu_list     = (const float*)d_in[12];
    const float* prices      = (const float*)d_in[13];
    const float* price_table = (const float*)d_in[14];
    const int*   item_ids    = (const int*)d_in[15];
    const int*   itemset     = (const int*)d_in[16];
    const int*   userid      = (const int*)d_in[17];

    fused_kernel<<<NTOT, 256>>>(alpha, rho, lam, beta, mu_tab, theta, gamma,
                                w1, b1, w2, b2, sigma_list, mu_list,
                                prices, price_table, item_ids, itemset, userid,
                                (float*)d_out);
}

// round 15
// speedup vs baseline: 1.4262x; 1.1649x over previous
#include <cuda_runtime.h>
#include <math.h>
#include <stdint.h>

// Problem constants (fixed by the benchmark)
#define BB 64
#define TT 20
#define KK 50
#define EE 100
#define HH 64
#define NROWS (5*BB*KK + 2*BB)    // 16128 gathered rows
#define RROWS 64                  // rows per block in rows role (4x4 tiles)
#define NBLK_ROWS (NROWS/RROWS)   // 252
#define NBLK_BASK (BB*10)         // 640: (b, t-pair), 8 warps

// block-role layout: producers first, then rows/basket alternating
#define ROLE_A_BASE    0                   // 64 blocks
#define ROLE_RDA0_BASE (ROLE_A_BASE+BB)    // 64
#define ROLE_P_BASE    (ROLE_RDA0_BASE+BB) // 128
#define ROLE_KES_BASE  (ROLE_P_BASE+BB)    // 192
#define ROLE_MIX_BASE  (ROLE_KES_BASE+BB)  // 256
#define NTOT           (ROLE_MIX_BASE + NBLK_ROWS + NBLK_BASK) // 1148

// ---------------- scratch (no allocations allowed) ----------------
__device__ float g_A[BB*KK*KK];     // A[b,k,j] = alpha_c[k] . rho_c[j]
__device__ float g_rda0[BB*TT*KK];  // rho_c[j] . alpha_item0[t]
__device__ float g_P[BB*TT*KK];     // rho_item0[t] . alpha_c[k]
__device__ float g_ra00[BB*TT];     // rho_item0 . alpha_item0
__device__ float g_kesc[BB*KK];
__device__ float g_kes0[BB*TT];
__device__ float g_part_rows[NBLK_ROWS];
__device__ float g_part_bask[NBLK_BASK];
__device__ unsigned g_ready[BB];    // per-b producer count (4 expected); reset by last block
__device__ unsigned g_count;        // completion ticket; reset by last block

// order-preserving float<->int map (self-inverse)
__device__ __forceinline__ int f_ord(float f) {
    int i = __float_as_int(f);
    return i ^ ((i >> 31) & 0x7FFFFFFF);
}
__device__ __forceinline__ float ord_f(int i) {
    i ^= ((i >> 31) & 0x7FFFFFFF);
    return __int_as_float(i);
}

// =====================================================================
// One fused kernel: producers first; rows (4x4-tiled) & basket
// (table-driven, deferred epilogue) interleaved by bid.
// =====================================================================
__global__ void __launch_bounds__(256, 5) fused_kernel(
    const float* __restrict__ alpha, const float* __restrict__ rho,
    const float* __restrict__ lam,   const float* __restrict__ beta,
    const float* __restrict__ mu_tab,const float* __restrict__ theta,
    const float* __restrict__ gamma,
    const float* __restrict__ w1, const float* __restrict__ b1,
    const float* __restrict__ w2, const float* __restrict__ b2,
    const float* __restrict__ sigma, const float* __restrict__ mu,
    const float* __restrict__ prices, const float* __restrict__ price_table,
    const int* __restrict__ item_ids, const int* __restrict__ itemset,
    const int* __restrict__ userid, float* __restrict__ out)
{
    __shared__ __align__(16) char smem_raw[43008];
    __shared__ float ws[8];
    __shared__ double wd[8];
    __shared__ int is_last;
    const unsigned FULL = 0xffffffffu;
    int bx = blockIdx.x, tid = threadIdx.x;

    // role resolution for mixed region (strict alternation, then basket tail)
    int rows_idx = -1, bask_idx = -1;
    if (bx >= ROLE_MIX_BASE) {
        int i = bx - ROLE_MIX_BASE;
        if (i < 2*NBLK_ROWS) { if ((i & 1) == 0) rows_idx = i >> 1; else bask_idx = i >> 1; }
        else                 bask_idx = NBLK_ROWS + (i - 2*NBLK_ROWS);
    }

    if (bx < ROLE_RDA0_BASE) {
        // ============ A[b,k,j] Gram, 4x4 tiles ============
        int b = bx - ROLE_A_BASE;
        float* sA = (float*)smem_raw;      // [e][k] pitch 52
        float* sR = sA + EE*52;
        for (int i = tid; i < 2*EE; i += 256) { int e = i >> 1, k = 50 + (i & 1); sA[e*52+k]=0.f; sR[e*52+k]=0.f; }
        for (int i = tid; i < KK*EE; i += 256) {
            int k = i / EE, e = i - k*EE; int row = itemset[b*KK + k];
            sA[e*52 + k] = alpha[(size_t)row*EE + e];
            sR[e*52 + k] = rho  [(size_t)row*EE + e];
        }
        __syncthreads();
        if (tid < 169) {
            int ty = tid / 13, tx = tid - ty*13;
            float acc[4][4] = {};
            for (int e = 0; e < EE; e++) {
                float4 av = *(const float4*)&sA[e*52 + ty*4];
                float4 rv = *(const float4*)&sR[e*52 + tx*4];
                float aa[4] = {av.x, av.y, av.z, av.w};
                float rr[4] = {rv.x, rv.y, rv.z, rv.w};
                #pragma unroll
                for (int i = 0; i < 4; i++)
                    #pragma unroll
                    for (int j = 0; j < 4; j++) acc[i][j] = fmaf(aa[i], rr[j], acc[i][j]);
            }
            #pragma unroll
            for (int i = 0; i < 4; i++) {
                int k = ty*4 + i; if (k >= KK) break;
                #pragma unroll
                for (int j = 0; j < 4; j++) {
                    int jj = tx*4 + j;
                    if (jj < KK) g_A[(b*KK + k)*KK + jj] = acc[i][j];
                }
            }
        }
        __syncthreads();
        if (tid == 0) { __threadfence(); atomicAdd(&g_ready[b], 1u); }

    } else if (bx < ROLE_P_BASE) {
        // ============ rda0[b,t,j] = alpha_item0[t] . rho_c[j] ============
        int b = bx - ROLE_RDA0_BASE;
        float* sR  = (float*)smem_raw;     // [e][j] pitch 52
        float* sA0 = sR + EE*52;           // [e][t] pitch 20
        for (int i = tid; i < 2*EE; i += 256) { int e = i >> 1, k = 50 + (i & 1); sR[e*52+k]=0.f; }
        for (int i = tid; i < KK*EE; i += 256) {
            int k = i / EE, e = i - k*EE; int row = itemset[b*KK + k];
            sR[e*52 + k] = rho[(size_t)row*EE + e];
        }
        for (int i = tid; i < TT*EE; i += 256) {
            int t = i / EE, e = i - t*EE; int row = item_ids[b*TT + t];
            sA0[e*20 + t] = alpha[(size_t)row*EE + e];
        }
        __syncthreads();
        if (tid < 65) {
            int ty = tid / 13, tx = tid - ty*13;
            float acc[4][4] = {};
            for (int e = 0; e < EE; e++) {
                float4 av = *(const float4*)&sA0[e*20 + ty*4];
                float4 rv = *(const float4*)&sR[e*52 + tx*4];
                float aa[4] = {av.x, av.y, av.z, av.w};
                float rr[4] = {rv.x, rv.y, rv.z, rv.w};
                #pragma unroll
                for (int i = 0; i < 4; i++)
                    #pragma unroll
                    for (int j = 0; j < 4; j++) acc[i][j] = fmaf(aa[i], rr[j], acc[i][j]);
            }
            #pragma unroll
            for (int i = 0; i < 4; i++) {
                int t = ty*4 + i;
                #pragma unroll
                for (int j = 0; j < 4; j++) {
                    int jj = tx*4 + j;
                    if (jj < KK) g_rda0[(b*TT + t)*KK + jj] = acc[i][j];
                }
            }
        }
        __syncthreads();
        if (tid == 0) { __threadfence(); atomicAdd(&g_ready[b], 1u); }

    } else if (bx < ROLE_KES_BASE) {
        // ============ P[b,t,k] = rho_item0[t] . alpha_c[k]; ra00 ============
        int b = bx - ROLE_P_BASE;
        float* sAC = (float*)smem_raw;     // [e][k] pitch 52
        float* sR0 = sAC + EE*52;          // [e][t] pitch 20
        float* sA0 = sR0 + EE*20;
        for (int i = tid; i < 2*EE; i += 256) { int e = i >> 1, k = 50 + (i & 1); sAC[e*52+k]=0.f; }
        for (int i = tid; i < KK*EE; i += 256) {
            int k = i / EE, e = i - k*EE; int row = itemset[b*KK + k];
            sAC[e*52 + k] = alpha[(size_t)row*EE + e];
        }
        for (int i = tid; i < TT*EE; i += 256) {
            int t = i / EE, e = i - t*EE; int row = item_ids[b*TT + t];
            sR0[e*20 + t] = rho  [(size_t)row*EE + e];
            sA0[e*20 + t] = alpha[(size_t)row*EE + e];
        }
        __syncthreads();
        if (tid < 65) {
            int ty = tid / 13, tx = tid - ty*13;
            float acc[4][4] = {};
            for (int e = 0; e < EE; e++) {
                float4 rv = *(const float4*)&sR0[e*20 + ty*4];
                float4 av = *(const float4*)&sAC[e*52 + tx*4];
                float rr[4] = {rv.x, rv.y, rv.z, rv.w};
                float aa[4] = {av.x, av.y, av.z, av.w};
                #pragma unroll
                for (int i = 0; i < 4; i++)
                    #pragma unroll
                    for (int j = 0; j < 4; j++) acc[i][j] = fmaf(rr[i], aa[j], acc[i][j]);
            }
            #pragma unroll
            for (int i = 0; i < 4; i++) {
                int t = ty*4 + i;
                #pragma unroll
                for (int j = 0; j < 4; j++) {
                    int kk = tx*4 + j;
                    if (kk < KK) g_P[(b*TT + t)*KK + kk] = acc[i][j];
                }
            }
        }
        if (tid >= 96 && tid < 96 + TT) {
            int t = tid - 96;
            float s = 0.f;
            for (int e = 0; e < EE; e++) s = fmaf(sR0[e*20 + t], sA0[e*20 + t], s);
            g_ra00[b*TT + t] = s;
        }
        __syncthreads();
        if (tid == 0) { __threadfence(); atomicAdd(&g_ready[b], 1u); }

    } else if (bx < ROLE_MIX_BASE) {
        // ============ kes role, one block per b (70 entries, 8 warps) ============
        int b = bx - ROLE_KES_BASE;
        int w = tid >> 5, lane = tid & 31;
        int u = userid[b];
        const float* th = theta + (size_t)u*EE;
        const float* ga = gamma + (size_t)u*EE;
        float th0 = th[lane], th1 = th[32+lane], th2 = th[64+lane];
        float ga0 = ga[lane], ga1 = ga[32+lane], ga2 = ga[64+lane];
        float th3 = (lane < 4) ? th[96+lane] : 0.f;
        float ga3 = (lane < 4) ? ga[96+lane] : 0.f;

        for (int e = w; e < KK + TT; e += 8) {
            int idx; float price; bool is_c = (e < KK);
            if (is_c) { idx = itemset[b*KK + e]; price = price_table[idx]; }
            else      { int t = e - KK; idx = item_ids[b*TT + t]; price = prices[b*TT + t]; }
            const float* a  = alpha + (size_t)idx*EE;
            const float* l  = lam   + (size_t)idx*EE;
            const float* be = beta  + (size_t)idx*EE;
            float a0 = a[lane], a1 = a[32+lane], a2 = a[64+lane];
            float l0 = l[lane], l1 = l[32+lane], l2 = l[64+lane];
            float be0 = be[lane], be1 = be[32+lane], be2 = be[64+lane];
            float a3 = 0.f, l3 = 0.f, be3 = 0.f;
            if (lane < 4) { a3 = a[96+lane]; l3 = l[96+lane]; be3 = be[96+lane]; }

            float s1 = l0 + l1 + l2 + l3;
            float s2 = fmaf(th0,a0, fmaf(th1,a1, fmaf(th2,a2, th3*a3)));
            float s3 = fmaf(ga0,be0, fmaf(ga1,be1, fmaf(ga2,be2, ga3*be3)));
            #pragma unroll
            for (int o = 16; o; o >>= 1) {
                s1 += __shfl_xor_sync(FULL, s1, o);
                s2 += __shfl_xor_sync(FULL, s2, o);
                s3 += __shfl_xor_sync(FULL, s3, o);
            }
            if (lane == 0) {
                float val = (s1 + s2) * (1.f/EE) - (s3 * (1.f/EE)) * logf(price);
                if (is_c) g_kesc[b*KK + e] = val; else g_kes0[b*TT + (e - KK)] = val;
            }
        }
        __syncthreads();
        if (tid == 0) { __threadfence(); atomicAdd(&g_ready[b], 1u); }

    } else if (rows_idx >= 0) {
        // ============ rows role: Qf + prior, 64 rows, 4x4 tiles, w1 e-chunked ====
        float* w1t   = (float*)smem_raw;        // [el][h] pitch 68 (chunk of 50 e)
        float* v_rm  = w1t + 50*68;             // [e][row] pitch 68 (full 100 e x 64 rows)
        float* ssrow = v_rm + EE*68;            // 64
        float* w2s   = ssrow + RROWS;           // 64
        float* b1s   = w2s + HH;                // 64
        float* bsum  = b1s + HH;                // 1

        int base = rows_idx * RROWS;
        int g; const float* tab; int uoff = 0;
        if (base < 5*BB*KK) {
            g = base / (BB*KK);
            tab = (g==0)?alpha : (g==1)?rho : (g==2)?lam : (g==3)?beta : mu_tab;
        } else if (base < 5*BB*KK + BB) { g = 5; tab = theta; uoff = base - 5*BB*KK; }
        else                            { g = 6; tab = gamma; uoff = base - 5*BB*KK - BB; }
        float sg = sigma[g], muv = mu[g];
        float b2v = b2[0];

        if (tid < HH) { w2s[tid] = w2[tid]; b1s[tid] = b1[tid]; }
        if (tid == 0) *bsum = 0.f;

        // gather 64 rows, transposed [e][row]
        for (int i = tid; i < RROWS*EE; i += 256) {
            int rl = i / EE, e = i - rl*EE;
            int idx;
            if (g < 5) idx = itemset[base - g*(BB*KK) + rl];
            else       idx = userid[uoff + rl];
            v_rm[e*68 + rl] = tab[(size_t)idx*EE + e];
        }
        __syncthreads();

        // prior sums, one thread per row (lane-stride-1: conflict-free)
        if (tid < RROWS) {
            float ss = 0.f;
            for (int e = 0; e < EE; e++) { float x = v_rm[e*68 + tid] - muv; ss = fmaf(x, x, ss); }
            ssrow[tid] = ss;
        }

        // 4 rows x 4 hidden per thread: ty in [0,16) row-group, tx in [0,16) col-group
        int ty = tid >> 4, tx = tid & 15;
        float acc[4][4];
        #pragma unroll
        for (int i = 0; i < 4; i++)
            #pragma unroll
            for (int j = 0; j < 4; j++) acc[i][j] = b1s[tx*4 + j];

        for (int c = 0; c < 2; c++) {
            if (c) __syncthreads();
            for (int i = tid; i < HH*50; i += 256) {
                int h = i / 50, el = i - h*50;
                w1t[el*68 + h] = w1[h*EE + c*50 + el];
            }
            __syncthreads();
            for (int el = 0; el < 50; el++) {
                float4 wv = *(const float4*)&w1t[el*68 + tx*4];
                float4 vv = *(const float4*)&v_rm[(c*50 + el)*68 + ty*4];
                float vr[4] = {vv.x, vv.y, vv.z, vv.w};
                float wr[4] = {wv.x, wv.y, wv.z, wv.w};
                #pragma unroll
                for (int i = 0; i < 4; i++)
                    #pragma unroll
                    for (int j = 0; j < 4; j++) acc[i][j] = fmaf(vr[i], wr[j], acc[i][j]);
            }
        }

        float z[4];
        #pragma unroll
        for (int i = 0; i < 4; i++) {
            float s = 0.f;
            #pragma unroll
            for (int j = 0; j < 4; j++) s = fmaf(fmaxf(acc[i][j], 0.f), w2s[tx*4 + j], s);
            z[i] = s;
        }
        #pragma unroll
        for (int o = 8; o; o >>= 1)
            #pragma unroll
            for (int i = 0; i < 4; i++) z[i] += __shfl_xor_sync(FULL, z[i], o);

        __syncthreads();   // ssrow ready (and w1t no longer needed)
        if (tx == 0) {
            float local = 0.f;
            #pragma unroll
            for (int i = 0; i < 4; i++) {
                float q = 1.f / (1.f + expf(-(z[i] + b2v)));
                local += (-0.5f/sg)*ssrow[ty*4 + i] - q;
            }
            atomicAdd(bsum, local);
        }
        __syncthreads();
        if (tid == 0) g_part_rows[rows_idx] = *bsum;

    } else {
        // ============ basket role: 2 t's x 4 k-chunks per block ============
        int bx2 = bask_idx;                 // 0..639
        int b = bx2 / 10, pair = bx2 % 10;
        int w = tid >> 5, lane = tid & 31;
        int sub = w >> 2, chunk = w & 3;
        int t = pair*2 + sub;
        int bt = b*TT + t;
        int base = b*KK;
        // balanced chunk bounds (cost = KS + 3*(KE-KS)): {0,21,35,44,50}
        int kstart = (chunk==0) ? 0  : (chunk==1) ? 21 : (chunk==2) ? 35 : 44;
        int kend   = (chunk==0) ? 21 : (chunk==1) ? 35 : (chunk==2) ? 44 : 50;

        // inputs not produced in-kernel can be read pre-wait
        int item0 = item_ids[bt];
        bool v1 = (lane < KK - 32);
        int c0i = itemset[base + lane];
        int c1i = v1 ? itemset[base + 32 + lane] : 0;
        bool mj0 = (c0i != item0);
        bool mj1 = v1 && (c1i != item0);
        unsigned ball0 = __ballot_sync(FULL, mj0);
        unsigned ball1 = __ballot_sync(FULL, mj1);
        int popA = __popc(ball0);

        // wait for this b's producers (A, rda0, P, kes)
        if (tid == 0) {
            volatile unsigned* f = &g_ready[b];
            while (*f < 4u) __nanosleep(64);
        }
        __syncthreads();
        __threadfence();

        float* sA   = (float*)smem_raw;     // A[b] [k][j], 10KB
        float* rtab = sA + KK*KK;           // rdenom table indexed by cnt (0..50)
        for (int i = tid; i < KK*KK; i += 256) sA[i] = g_A[base*KK + i];
        if (tid <= 50) rtab[tid] = 1.f / ((float)(tid + 2) * (float)EE);

        float kesc0 = g_kesc[base + lane];
        float kesc1 = v1 ? g_kesc[base + 32 + lane] : 0.f;
        float rj0 = g_rda0[bt*KK + lane];
        float rj1 = v1 ? g_rda0[bt*KK + 32 + lane] : 0.f;
        float ra00  = g_ra00[bt];
        float kes0v = g_kes0[bt];

        // one-time masked inclusive prefix scan of P over k (two 32-halves)
        float px0 = mj0 ? g_P[bt*KK + lane] : 0.f;
        float px1 = mj1 ? g_P[bt*KK + 32 + lane] : 0.f;
        #pragma unroll
        for (int d = 1; d < 32; d <<= 1) {
            float v = __shfl_up_sync(FULL, px0, d);
            if (lane >= d) px0 += v;
        }
        float tot0 = __shfl_sync(FULL, px0, 31);
        #pragma unroll
        for (int d = 1; d < 32; d <<= 1) {
            float v = __shfl_up_sync(FULL, px1, d);
            if (lane >= d) px1 += v;
        }
        px1 += tot0;

        __syncthreads();   // sA + rtab ready

        // chunk base: Cj up to kstart (cheap pipelined masked FMAs)
        float Cj0 = 0.f, Cj1 = 0.f;
        for (int k = 0; k < kstart; k++) {
            float mf = ((k < 32 ? (ball0 >> k) : (ball1 >> (k-32))) & 1u) ? 1.f : 0.f;
            Cj0 = fmaf(mf, sA[k*KK + lane], Cj0);
            if (v1) Cj1 = fmaf(mf, sA[k*KK + 32 + lane], Cj1);
        }
        int cnt;
        if (kstart == 0)        cnt = 0;
        else if (kstart <= 32)  cnt = __popc(ball0 & ((1u << kstart) - 1u));
        else                    cnt = popA + __popc(ball1 & ((1u << (kstart-32)) - 1u));

        // lean serial loop: maxes only; designated-lane state captured, epilogue deferred
        int   sM0i = 0, sMci = 0, sCnt = -1;
        float sC = 0.f; int sK = 0;
        for (int k = kstart; k < kend; k++) {
            bool mk = ((k < 32 ? (ball0 >> k) : (ball1 >> (k-32))) & 1u);
            if (mk) {
                cnt++;
                float ak0 = sA[k*KK + lane];
                float ak1 = v1 ? sA[k*KK + 32 + lane] : 0.f;
                Cj0 += ak0;
                Cj1 += ak1;

                float rdenom = rtab[cnt];

                float c0 = -INFINITY, cc = -INFINITY;
                if (mj0 && lane > k) {
                    float bs = rj0 + Cj0;
                    c0 = fmaf(bs + rj0, rdenom, kesc0);
                    cc = fmaf(bs + ak0, rdenom, kesc0);
                }
                if (mj1 && (lane + 32) > k) {
                    float bs = rj1 + Cj1;
                    float y0 = fmaf(bs + rj1, rdenom, kesc1);
                    float yc = fmaf(bs + ak1, rdenom, kesc1);
                    c0 = fmaxf(c0, y0); cc = fmaxf(cc, yc);
                }

                int m0i = __reduce_max_sync(FULL, f_ord(c0));
                int mci = __reduce_max_sync(FULL, f_ord(cc));

                if (lane == (k & 31)) {     // designated j==k (each lane <=1x per chunk)
                    sM0i = m0i; sMci = mci; sCnt = cnt; sK = k;
                    sC = (k < 32) ? Cj0 : Cj1;
                }
            }
        }

        // deferred epilogue: all designated lanes compute log-sigmoid in parallel
        float acc = 0.f;
        if (sCnt >= 0) {
            float m0 = ord_f(sM0i);
            float mc = ord_f(sMci);
            bool lo = (sK < 32);
            float kescd = lo ? kesc0 : kesc1;
            float rjd   = lo ? rj0   : rj1;
            float Pcd   = lo ? px0   : px1;
            float lenk  = 1.f + (float)sCnt;
            float inv = __fdividef(1.f, (float)EE * lenk);
            float i0v = (ra00 + Pcd) * inv;
            float icv = (rjd  + sC) * inv;
            float Kes0 = kes0v + i0v + fmaxf(0.f, m0);
            float KesC = kescd + icv + fmaxf(0.f, mc);
            float xq = Kes0 - KesC;
            acc = fminf(xq, 0.f) - log1pf(expf(-fabsf(xq)));
        }

        #pragma unroll
        for (int o = 16; o; o >>= 1) acc += __shfl_xor_sync(FULL, acc, o);
        if (lane == 0) ws[w] = acc;
        __syncthreads();
        if (tid == 0) {
            float s = 0.f;
            #pragma unroll
            for (int i = 0; i < 8; i++) s += ws[i];
            g_part_bask[bx2] = s;
        }
    }

    // ================= common epilogue: completion ticket =================
    __syncthreads();
    if (tid == 0) {
        __threadfence();
        unsigned tk = atomicAdd(&g_count, 1u);
        is_last = (tk == NTOT - 1) ? 1 : 0;
    }
    __syncthreads();

    if (is_last) {
        __threadfence();  // see all blocks' partial stores
        double s = 0.0;
        for (int i = tid; i < NBLK_ROWS; i += 256) s += (double)g_part_rows[i];
        for (int i = tid; i < NBLK_BASK; i += 256) s += (double)g_part_bask[i];
        #pragma unroll
        for (int o = 16; o; o >>= 1) s += __shfl_xor_sync(FULL, s, o);
        if ((tid & 31) == 0) wd[tid >> 5] = s;
        __syncthreads();
        if (tid == 0) {
            double tt = 0.0;
            #pragma unroll
            for (int i = 0; i < 8; i++) tt += wd[i];
            out[0] = (float)tt;
            g_count = 0u;                       // reset for next replay
        }
        if (tid < BB) g_ready[tid] = 0u;        // reset flags for next replay
    }
}

// ================= launch: ONE node, no driver objects ================
extern "C" void kernel_launch(void* const* d_in, const int* in_sizes, int n_in,
                              void* d_out, int out_size)
{
    const float* alpha       = (const float*)d_in[0];
    const float* rho         = (const float*)d_in[1];
    const float* lam         = (const float*)d_in[2];
    const float* beta        = (const float*)d_in[3];
    const float* mu_tab      = (const float*)d_in[4];
    const float* theta       = (const float*)d_in[5];
    const float* gamma       = (const float*)d_in[6];
    const float* w1          = (const float*)d_in[7];
    const float* b1          = (const float*)d_in[8];
    const float* w2          = (const float*)d_in[9];
    const float* b2          = (const float*)d_in[10];
    const float* sigma_list  = (const float*)d_in[11];
    const float* mu_list     = (const float*)d_in[12];
    const float* prices      = (const float*)d_in[13];
    const float* price_table = (const float*)d_in[14];
    const int*   item_ids    = (const int*)d_in[15];
    const int*   itemset     = (const int*)d_in[16];
    const int*   userid      = (const int*)d_in[17];

    fused_kernel<<<NTOT, 256>>>(alpha, rho, lam, beta, mu_tab, theta, gamma,
                                w1, b1, w2, b2, sigma_list, mu_list,
                                prices, price_table, item_ids, itemset, userid,
                                (float*)d_out);
}

// round 16
// speedup vs baseline: 1.5017x; 1.0530x over previous
#include <cuda_runtime.h>
#include <math.h>
#include <stdint.h>

// Problem constants (fixed by the benchmark)
#define BB 64
#define TT 20
#define KK 50
#define EE 100
#define HH 64
#define NROWS (5*BB*KK + 2*BB)    // 16128 gathered rows
#define RROWS 64                  // rows per block in rows role (4x4 tiles)
#define NBLK_ROWS (NROWS/RROWS)   // 252
#define NBLK_BASK (BB*10)         // 640: (b, t-pair), 8 warps

// block-role layout: producers first, then rows/basket alternating
#define ROLE_A_BASE    0                   // 64 blocks
#define ROLE_RDA0_BASE (ROLE_A_BASE+BB)    // 64
#define ROLE_P_BASE    (ROLE_RDA0_BASE+BB) // 128
#define ROLE_KES_BASE  (ROLE_P_BASE+BB)    // 192
#define ROLE_MIX_BASE  (ROLE_KES_BASE+BB)  // 256
#define NTOT           (ROLE_MIX_BASE + NBLK_ROWS + NBLK_BASK) // 1148

// ---------------- scratch (no allocations allowed) ----------------
__device__ float g_A[BB*KK*KK];     // A[b,k,j] = alpha_c[k] . rho_c[j]
__device__ float g_rda0[BB*TT*KK];  // rho_c[j] . alpha_item0[t]
__device__ float g_P[BB*TT*KK];     // rho_item0[t] . alpha_c[k]
__device__ float g_ra00[BB*TT];     // rho_item0 . alpha_item0
__device__ float g_kesc[BB*KK];
__device__ float g_kes0[BB*TT];
__device__ float g_part_rows[NBLK_ROWS];
__device__ float g_part_bask[NBLK_BASK];
__device__ unsigned g_ready[BB];    // per-b producer count (4 expected); reset by last block
__device__ unsigned g_count;        // completion ticket; reset by last block

// order-preserving float<->int map (self-inverse)
__device__ __forceinline__ int f_ord(float f) {
    int i = __float_as_int(f);
    return i ^ ((i >> 31) & 0x7FFFFFFF);
}
__device__ __forceinline__ float ord_f(int i) {
    i ^= ((i >> 31) & 0x7FFFFFFF);
    return __int_as_float(i);
}

// =====================================================================
// One fused kernel: producers first; rows (4x4-tiled) & basket
// (block-scan chunk bases, table rdenoms, deferred epilogue) interleaved.
// =====================================================================
__global__ void __launch_bounds__(256, 5) fused_kernel(
    const float* __restrict__ alpha, const float* __restrict__ rho,
    const float* __restrict__ lam,   const float* __restrict__ beta,
    const float* __restrict__ mu_tab,const float* __restrict__ theta,
    const float* __restrict__ gamma,
    const float* __restrict__ w1, const float* __restrict__ b1,
    const float* __restrict__ w2, const float* __restrict__ b2,
    const float* __restrict__ sigma, const float* __restrict__ mu,
    const float* __restrict__ prices, const float* __restrict__ price_table,
    const int* __restrict__ item_ids, const int* __restrict__ itemset,
    const int* __restrict__ userid, float* __restrict__ out)
{
    __shared__ __align__(16) char smem_raw[43008];
    __shared__ float ws[8];
    __shared__ double wd[8];
    __shared__ int is_last;
    const unsigned FULL = 0xffffffffu;
    int bx = blockIdx.x, tid = threadIdx.x;

    // role resolution for mixed region (strict alternation, then basket tail)
    int rows_idx = -1, bask_idx = -1;
    if (bx >= ROLE_MIX_BASE) {
        int i = bx - ROLE_MIX_BASE;
        if (i < 2*NBLK_ROWS) { if ((i & 1) == 0) rows_idx = i >> 1; else bask_idx = i >> 1; }
        else                 bask_idx = NBLK_ROWS + (i - 2*NBLK_ROWS);
    }

    if (bx < ROLE_RDA0_BASE) {
        // ============ A[b,k,j] Gram, 4x4 tiles ============
        int b = bx - ROLE_A_BASE;
        float* sA = (float*)smem_raw;      // [e][k] pitch 52
        float* sR = sA + EE*52;
        for (int i = tid; i < 2*EE; i += 256) { int e = i >> 1, k = 50 + (i & 1); sA[e*52+k]=0.f; sR[e*52+k]=0.f; }
        for (int i = tid; i < KK*EE; i += 256) {
            int k = i / EE, e = i - k*EE; int row = itemset[b*KK + k];
            sA[e*52 + k] = alpha[(size_t)row*EE + e];
            sR[e*52 + k] = rho  [(size_t)row*EE + e];
        }
        __syncthreads();
        if (tid < 169) {
            int ty = tid / 13, tx = tid - ty*13;
            float acc[4][4] = {};
            for (int e = 0; e < EE; e++) {
                float4 av = *(const float4*)&sA[e*52 + ty*4];
                float4 rv = *(const float4*)&sR[e*52 + tx*4];
                float aa[4] = {av.x, av.y, av.z, av.w};
                float rr[4] = {rv.x, rv.y, rv.z, rv.w};
                #pragma unroll
                for (int i = 0; i < 4; i++)
                    #pragma unroll
                    for (int j = 0; j < 4; j++) acc[i][j] = fmaf(aa[i], rr[j], acc[i][j]);
            }
            #pragma unroll
            for (int i = 0; i < 4; i++) {
                int k = ty*4 + i; if (k >= KK) break;
                #pragma unroll
                for (int j = 0; j < 4; j++) {
                    int jj = tx*4 + j;
                    if (jj < KK) g_A[(b*KK + k)*KK + jj] = acc[i][j];
                }
            }
        }
        __syncthreads();
        if (tid == 0) { __threadfence(); atomicAdd(&g_ready[b], 1u); }

    } else if (bx < ROLE_P_BASE) {
        // ============ rda0[b,t,j] = alpha_item0[t] . rho_c[j] ============
        int b = bx - ROLE_RDA0_BASE;
        float* sR  = (float*)smem_raw;     // [e][j] pitch 52
        float* sA0 = sR + EE*52;           // [e][t] pitch 20
        for (int i = tid; i < 2*EE; i += 256) { int e = i >> 1, k = 50 + (i & 1); sR[e*52+k]=0.f; }
        for (int i = tid; i < KK*EE; i += 256) {
            int k = i / EE, e = i - k*EE; int row = itemset[b*KK + k];
            sR[e*52 + k] = rho[(size_t)row*EE + e];
        }
        for (int i = tid; i < TT*EE; i += 256) {
            int t = i / EE, e = i - t*EE; int row = item_ids[b*TT + t];
            sA0[e*20 + t] = alpha[(size_t)row*EE + e];
        }
        __syncthreads();
        if (tid < 65) {
            int ty = tid / 13, tx = tid - ty*13;
            float acc[4][4] = {};
            for (int e = 0; e < EE; e++) {
                float4 av = *(const float4*)&sA0[e*20 + ty*4];
                float4 rv = *(const float4*)&sR[e*52 + tx*4];
                float aa[4] = {av.x, av.y, av.z, av.w};
                float rr[4] = {rv.x, rv.y, rv.z, rv.w};
                #pragma unroll
                for (int i = 0; i < 4; i++)
                    #pragma unroll
                    for (int j = 0; j < 4; j++) acc[i][j] = fmaf(aa[i], rr[j], acc[i][j]);
            }
            #pragma unroll
            for (int i = 0; i < 4; i++) {
                int t = ty*4 + i;
                #pragma unroll
                for (int j = 0; j < 4; j++) {
                    int jj = tx*4 + j;
                    if (jj < KK) g_rda0[(b*TT + t)*KK + jj] = acc[i][j];
                }
            }
        }
        __syncthreads();
        if (tid == 0) { __threadfence(); atomicAdd(&g_ready[b], 1u); }

    } else if (bx < ROLE_KES_BASE) {
        // ============ P[b,t,k] = rho_item0[t] . alpha_c[k]; ra00 ============
        int b = bx - ROLE_P_BASE;
        float* sAC = (float*)smem_raw;     // [e][k] pitch 52
        float* sR0 = sAC + EE*52;          // [e][t] pitch 20
        float* sA0 = sR0 + EE*20;
        for (int i = tid; i < 2*EE; i += 256) { int e = i >> 1, k = 50 + (i & 1); sAC[e*52+k]=0.f; }
        for (int i = tid; i < KK*EE; i += 256) {
            int k = i / EE, e = i - k*EE; int row = itemset[b*KK + k];
            sAC[e*52 + k] = alpha[(size_t)row*EE + e];
        }
        for (int i = tid; i < TT*EE; i += 256) {
            int t = i / EE, e = i - t*EE; int row = item_ids[b*TT + t];
            sR0[e*20 + t] = rho  [(size_t)row*EE + e];
            sA0[e*20 + t] = alpha[(size_t)row*EE + e];
        }
        __syncthreads();
        if (tid < 65) {
            int ty = tid / 13, tx = tid - ty*13;
            float acc[4][4] = {};
            for (int e = 0; e < EE; e++) {
                float4 rv = *(const float4*)&sR0[e*20 + ty*4];
                float4 av = *(const float4*)&sAC[e*52 + tx*4];
                float rr[4] = {rv.x, rv.y, rv.z, rv.w};
                float aa[4] = {av.x, av.y, av.z, av.w};
                #pragma unroll
                for (int i = 0; i < 4; i++)
                    #pragma unroll
                    for (int j = 0; j < 4; j++) acc[i][j] = fmaf(rr[i], aa[j], acc[i][j]);
            }
            #pragma unroll
            for (int i = 0; i < 4; i++) {
                int t = ty*4 + i;
                #pragma unroll
                for (int j = 0; j < 4; j++) {
                    int kk = tx*4 + j;
                    if (kk < KK) g_P[(b*TT + t)*KK + kk] = acc[i][j];
                }
            }
        }
        if (tid >= 96 && tid < 96 + TT) {
            int t = tid - 96;
            float s = 0.f;
            for (int e = 0; e < EE; e++) s = fmaf(sR0[e*20 + t], sA0[e*20 + t], s);
            g_ra00[b*TT + t] = s;
        }
        __syncthreads();
        if (tid == 0) { __threadfence(); atomicAdd(&g_ready[b], 1u); }

    } else if (bx < ROLE_MIX_BASE) {
        // ============ kes role, one block per b (70 entries, 8 warps) ============
        int b = bx - ROLE_KES_BASE;
        int w = tid >> 5, lane = tid & 31;
        int u = userid[b];
        const float* th = theta + (size_t)u*EE;
        const float* ga = gamma + (size_t)u*EE;
        float th0 = th[lane], th1 = th[32+lane], th2 = th[64+lane];
        float ga0 = ga[lane], ga1 = ga[32+lane], ga2 = ga[64+lane];
        float th3 = (lane < 4) ? th[96+lane] : 0.f;
        float ga3 = (lane < 4) ? ga[96+lane] : 0.f;

        for (int e = w; e < KK + TT; e += 8) {
            int idx; float price; bool is_c = (e < KK);
            if (is_c) { idx = itemset[b*KK + e]; price = price_table[idx]; }
            else      { int t = e - KK; idx = item_ids[b*TT + t]; price = prices[b*TT + t]; }
            const float* a  = alpha + (size_t)idx*EE;
            const float* l  = lam   + (size_t)idx*EE;
            const float* be = beta  + (size_t)idx*EE;
            float a0 = a[lane], a1 = a[32+lane], a2 = a[64+lane];
            float l0 = l[lane], l1 = l[32+lane], l2 = l[64+lane];
            float be0 = be[lane], be1 = be[32+lane], be2 = be[64+lane];
            float a3 = 0.f, l3 = 0.f, be3 = 0.f;
            if (lane < 4) { a3 = a[96+lane]; l3 = l[96+lane]; be3 = be[96+lane]; }

            float s1 = l0 + l1 + l2 + l3;
            float s2 = fmaf(th0,a0, fmaf(th1,a1, fmaf(th2,a2, th3*a3)));
            float s3 = fmaf(ga0,be0, fmaf(ga1,be1, fmaf(ga2,be2, ga3*be3)));
            #pragma unroll
            for (int o = 16; o; o >>= 1) {
                s1 += __shfl_xor_sync(FULL, s1, o);
                s2 += __shfl_xor_sync(FULL, s2, o);
                s3 += __shfl_xor_sync(FULL, s3, o);
            }
            if (lane == 0) {
                float val = (s1 + s2) * (1.f/EE) - (s3 * (1.f/EE)) * logf(price);
                if (is_c) g_kesc[b*KK + e] = val; else g_kes0[b*TT + (e - KK)] = val;
            }
        }
        __syncthreads();
        if (tid == 0) { __threadfence(); atomicAdd(&g_ready[b], 1u); }

    } else if (rows_idx >= 0) {
        // ============ rows role: Qf + prior, 64 rows, 4x4 tiles, w1 e-chunked ====
        float* w1t   = (float*)smem_raw;        // [el][h] pitch 68 (chunk of 50 e)
        float* v_rm  = w1t + 50*68;             // [e][row] pitch 68 (full 100 e x 64 rows)
        float* ssrow = v_rm + EE*68;            // 64
        float* w2s   = ssrow + RROWS;           // 64
        float* b1s   = w2s + HH;                // 64
        float* bsum  = b1s + HH;                // 1

        int base = rows_idx * RROWS;
        int g; const float* tab; int uoff = 0;
        if (base < 5*BB*KK) {
            g = base / (BB*KK);
            tab = (g==0)?alpha : (g==1)?rho : (g==2)?lam : (g==3)?beta : mu_tab;
        } else if (base < 5*BB*KK + BB) { g = 5; tab = theta; uoff = base - 5*BB*KK; }
        else                            { g = 6; tab = gamma; uoff = base - 5*BB*KK - BB; }
        float sg = sigma[g], muv = mu[g];
        float b2v = b2[0];

        if (tid < HH) { w2s[tid] = w2[tid]; b1s[tid] = b1[tid]; }
        if (tid == 0) *bsum = 0.f;

        // gather 64 rows, transposed [e][row]
        for (int i = tid; i < RROWS*EE; i += 256) {
            int rl = i / EE, e = i - rl*EE;
            int idx;
            if (g < 5) idx = itemset[base - g*(BB*KK) + rl];
            else       idx = userid[uoff + rl];
            v_rm[e*68 + rl] = tab[(size_t)idx*EE + e];
        }
        __syncthreads();

        // prior sums, one thread per row (lane-stride-1: conflict-free)
        if (tid < RROWS) {
            float ss = 0.f;
            for (int e = 0; e < EE; e++) { float x = v_rm[e*68 + tid] - muv; ss = fmaf(x, x, ss); }
            ssrow[tid] = ss;
        }

        // 4 rows x 4 hidden per thread
        int ty = tid >> 4, tx = tid & 15;
        float acc[4][4];
        #pragma unroll
        for (int i = 0; i < 4; i++)
            #pragma unroll
            for (int j = 0; j < 4; j++) acc[i][j] = b1s[tx*4 + j];

        for (int c = 0; c < 2; c++) {
            if (c) __syncthreads();
            for (int i = tid; i < HH*50; i += 256) {
                int h = i / 50, el = i - h*50;
                w1t[el*68 + h] = w1[h*EE + c*50 + el];
            }
            __syncthreads();
            for (int el = 0; el < 50; el++) {
                float4 wv = *(const float4*)&w1t[el*68 + tx*4];
                float4 vv = *(const float4*)&v_rm[(c*50 + el)*68 + ty*4];
                float vr[4] = {vv.x, vv.y, vv.z, vv.w};
                float wr[4] = {wv.x, wv.y, wv.z, wv.w};
                #pragma unroll
                for (int i = 0; i < 4; i++)
                    #pragma unroll
                    for (int j = 0; j < 4; j++) acc[i][j] = fmaf(vr[i], wr[j], acc[i][j]);
            }
        }

        float z[4];
        #pragma unroll
        for (int i = 0; i < 4; i++) {
            float s = 0.f;
            #pragma unroll
            for (int j = 0; j < 4; j++) s = fmaf(fmaxf(acc[i][j], 0.f), w2s[tx*4 + j], s);
            z[i] = s;
        }
        #pragma unroll
        for (int o = 8; o; o >>= 1)
            #pragma unroll
            for (int i = 0; i < 4; i++) z[i] += __shfl_xor_sync(FULL, z[i], o);

        __syncthreads();   // ssrow ready
        if (tx == 0) {
            float local = 0.f;
            #pragma unroll
            for (int i = 0; i < 4; i++) {
                float q = 1.f / (1.f + expf(-(z[i] + b2v)));
                local += (-0.5f/sg)*ssrow[ty*4 + i] - q;
            }
            atomicAdd(bsum, local);
        }
        __syncthreads();
        if (tid == 0) g_part_rows[rows_idx] = *bsum;

    } else {
        // ============ basket role: 2 t's x 4 EQUAL k-chunks; block-scan bases ====
        int bx2 = bask_idx;                 // 0..639
        int b = bx2 / 10, pair = bx2 % 10;
        int w = tid >> 5, lane = tid & 31;
        int sub = w >> 2, chunk = w & 3;
        int t = pair*2 + sub;
        int bt = b*TT + t;
        int base = b*KK;
        // equal chunk bounds: {0,13,25,38,50}
        int kstart = (chunk==0) ? 0  : (chunk==1) ? 13 : (chunk==2) ? 25 : 38;
        int kend   = (chunk==0) ? 13 : (chunk==1) ? 25 : (chunk==2) ? 38 : 50;

        // inputs not produced in-kernel can be read pre-wait
        int item0 = item_ids[bt];
        bool v1 = (lane < KK - 32);
        int c0i = itemset[base + lane];
        int c1i = v1 ? itemset[base + 32 + lane] : 0;
        bool mj0 = (c0i != item0);
        bool mj1 = v1 && (c1i != item0);
        unsigned ball0 = __ballot_sync(FULL, mj0);
        unsigned ball1 = __ballot_sync(FULL, mj1);
        int popA = __popc(ball0);

        // wait for this b's producers (A, rda0, P, kes)
        if (tid == 0) {
            volatile unsigned* f = &g_ready[b];
            while (*f < 4u) __nanosleep(64);
        }
        __syncthreads();
        __threadfence();

        float* sA   = (float*)smem_raw;     // A[b] [k][j], 10KB
        float* rtab = sA + KK*KK;           // rdenom table indexed by cnt (0..50)
        float* part = rtab + 64;            // [8 warps][64] chunk partial sums
        for (int i = tid; i < KK*KK; i += 256) sA[i] = g_A[base*KK + i];
        if (tid <= 50) rtab[tid] = 1.f / ((float)(tid + 2) * (float)EE);

        float kesc0 = g_kesc[base + lane];
        float kesc1 = v1 ? g_kesc[base + 32 + lane] : 0.f;
        float rj0 = g_rda0[bt*KK + lane];
        float rj1 = v1 ? g_rda0[bt*KK + 32 + lane] : 0.f;
        float ra00  = g_ra00[bt];
        float kes0v = g_kes0[bt];

        // one-time masked inclusive prefix scan of P over k (two 32-halves)
        float px0 = mj0 ? g_P[bt*KK + lane] : 0.f;
        float px1 = mj1 ? g_P[bt*KK + 32 + lane] : 0.f;
        #pragma unroll
        for (int d = 1; d < 32; d <<= 1) {
            float v = __shfl_up_sync(FULL, px0, d);
            if (lane >= d) px0 += v;
        }
        float tot0 = __shfl_sync(FULL, px0, 31);
        #pragma unroll
        for (int d = 1; d < 32; d <<= 1) {
            float v = __shfl_up_sync(FULL, px1, d);
            if (lane >= d) px1 += v;
        }
        px1 += tot0;

        __syncthreads();   // sA + rtab ready

        // pass 1: own-chunk masked partial sums (cheap pipelined FMAs)
        float p0 = 0.f, p1 = 0.f;
        for (int k = kstart; k < kend; k++) {
            float mf = ((k < 32 ? (ball0 >> k) : (ball1 >> (k-32))) & 1u) ? 1.f : 0.f;
            p0 = fmaf(mf, sA[k*KK + lane], p0);
            if (v1) p1 = fmaf(mf, sA[k*KK + 32 + lane], p1);
        }
        part[w*64 + lane]      = p0;
        part[w*64 + 32 + lane] = p1;
        __syncthreads();

        // chunk base = sum of preceding chunks' partials (same t)
        float Cj0 = 0.f, Cj1 = 0.f;
        for (int c = 0; c < chunk; c++) {
            Cj0 += part[(sub*4 + c)*64 + lane];
            Cj1 += part[(sub*4 + c)*64 + 32 + lane];
        }
        int cnt;
        if (kstart == 0)        cnt = 0;
        else if (kstart <= 32)  cnt = __popc(ball0 & ((1u << kstart) - 1u));
        else                    cnt = popA + __popc(ball1 & ((1u << (kstart-32)) - 1u));

        // lean serial loop: maxes only; designated-lane state captured, epilogue deferred
        int   sM0i = 0, sMci = 0, sCnt = -1;
        float sC = 0.f; int sK = 0;
        for (int k = kstart; k < kend; k++) {
            bool mk = ((k < 32 ? (ball0 >> k) : (ball1 >> (k-32))) & 1u);
            if (mk) {
                cnt++;
                float ak0 = sA[k*KK + lane];
                float ak1 = v1 ? sA[k*KK + 32 + lane] : 0.f;
                Cj0 += ak0;
                Cj1 += ak1;

                float rdenom = rtab[cnt];

                float c0 = -INFINITY, cc = -INFINITY;
                if (mj0 && lane > k) {
                    float bs = rj0 + Cj0;
                    c0 = fmaf(bs + rj0, rdenom, kesc0);
                    cc = fmaf(bs + ak0, rdenom, kesc0);
                }
                if (mj1 && (lane + 32) > k) {
                    float bs = rj1 + Cj1;
                    float y0 = fmaf(bs + rj1, rdenom, kesc1);
                    float yc = fmaf(bs + ak1, rdenom, kesc1);
                    c0 = fmaxf(c0, y0); cc = fmaxf(cc, yc);
                }

                int m0i = __reduce_max_sync(FULL, f_ord(c0));
                int mci = __reduce_max_sync(FULL, f_ord(cc));

                if (lane == (k & 31)) {     // designated j==k (each lane <=1x per chunk)
                    sM0i = m0i; sMci = mci; sCnt = cnt; sK = k;
                    sC = (k < 32) ? Cj0 : Cj1;
                }
            }
        }

        // deferred epilogue: all designated lanes compute log-sigmoid in parallel
        float acc = 0.f;
        if (sCnt >= 0) {
            float m0 = ord_f(sM0i);
            float mc = ord_f(sMci);
            bool lo = (sK < 32);
            float kescd = lo ? kesc0 : kesc1;
            float rjd   = lo ? rj0   : rj1;
            float Pcd   = lo ? px0   : px1;
            float lenk  = 1.f + (float)sCnt;
            float inv = __fdividef(1.f, (float)EE * lenk);
            float i0v = (ra00 + Pcd) * inv;
            float icv = (rjd  + sC) * inv;
            float Kes0 = kes0v + i0v + fmaxf(0.f, m0);
            float KesC = kescd + icv + fmaxf(0.f, mc);
            float xq = Kes0 - KesC;
            acc = fminf(xq, 0.f) - log1pf(expf(-fabsf(xq)));
        }

        #pragma unroll
        for (int o = 16; o; o >>= 1) acc += __shfl_xor_sync(FULL, acc, o);
        if (lane == 0) ws[w] = acc;
        __syncthreads();
        if (tid == 0) {
            float s = 0.f;
            #pragma unroll
            for (int i = 0; i < 8; i++) s += ws[i];
            g_part_bask[bx2] = s;
        }
    }

    // ================= common epilogue: completion ticket =================
    __syncthreads();
    if (tid == 0) {
        __threadfence();
        unsigned tk = atomicAdd(&g_count, 1u);
        is_last = (tk == NTOT - 1) ? 1 : 0;
    }
    __syncthreads();

    if (is_last) {
        __threadfence();  // see all blocks' partial stores
        double s = 0.0;
        for (int i = tid; i < NBLK_ROWS; i += 256) s += (double)g_part_rows[i];
        for (int i = tid; i < NBLK_BASK; i += 256) s += (double)g_part_bask[i];
        #pragma unroll
        for (int o = 16; o; o >>= 1) s += __shfl_xor_sync(FULL, s, o);
        if ((tid & 31) == 0) wd[tid >> 5] = s;
        __syncthreads();
        if (tid == 0) {
            double tt = 0.0;
            #pragma unroll
            for (int i = 0; i < 8; i++) tt += wd[i];
            out[0] = (float)tt;
            g_count = 0u;                       // reset for next replay
        }
        if (tid < BB) g_ready[tid] = 0u;        // reset flags for next replay
    }
}

// ================= launch: ONE node, no driver objects ================
extern "C" void kernel_launch(void* const* d_in, const int* in_sizes, int n_in,
                              void* d_out, int out_size)
{
    const float* alpha       = (const float*)d_in[0];
    const float* rho         = (const float*)d_in[1];
    const float* lam         = (const float*)d_in[2];
    const float* beta        = (const float*)d_in[3];
    const float* mu_tab      = (const float*)d_in[4];
    const float* theta       = (const float*)d_in[5];
    const float* gamma       = (const float*)d_in[6];
    const float* w1          = (const float*)d_in[7];
    const float* b1          = (const float*)d_in[8];
    const float* w2          = (const float*)d_in[9];
    const float* b2          = (const float*)d_in[10];
    const float* sigma_list  = (const float*)d_in[11];
    const float* mu_list     = (const float*)d_in[12];
    const float* prices      = (const float*)d_in[13];
    const float* price_table = (const float*)d_in[14];
    const int*   item_ids    = (const int*)d_in[15];
    const int*   itemset     = (const int*)d_in[16];
    const int*   userid      = (const int*)d_in[17];

    fused_kernel<<<NTOT, 256>>>(alpha, rho, lam, beta, mu_tab, theta, gamma,
                                w1, b1, w2, b2, sigma_list, mu_list,
                                prices, price_table, item_ids, itemset, userid,
                                (float*)d_out);
}